// round 1
// baseline (speedup 1.0000x reference)
#include <cuda_runtime.h>

#define BB 8
#define SS 1024
#define DD 512
#define HH 8
#define DHH 64
#define MTOT (BB*SS)   // 8192
#define BH   (BB*HH)   // 64

// ---------------- scratch (__device__ globals; no allocation allowed) ----------
__device__ float g_qu[MTOT*DD];                 // q + u_bias
__device__ float g_qv[MTOT*DD];                 // q + v_bias
__device__ float g_k [MTOT*DD];
__device__ float g_v [MTOT*DD];
__device__ float g_p [MTOT*DD];
__device__ float g_C [BH*SS*SS];                // content scores -> attention (256 MB)
__device__ float g_M [BH*SS*SS];                // pos scores pre-shift        (256 MB)
__device__ float g_ctx[MTOT*DD];

// ---------------- kernel 1: projection GEMM  C[M,512] = A[M,512]@W[512,512] ----
__global__ void proj_kernel(const float* __restrict__ A, const float* __restrict__ W,
                            const float* __restrict__ bias,
                            float* __restrict__ out0, const float* __restrict__ ex0,
                            float* __restrict__ out1, const float* __restrict__ ex1)
{
    __shared__ float As[16][65];   // As[k][m]
    __shared__ float Bs[16][68];   // Bs[k][n]
    const int tx = threadIdx.x & 15, ty = threadIdx.x >> 4;
    const int m0 = blockIdx.y * 64, n0 = blockIdx.x * 64;
    const int la_r = threadIdx.x >> 2;
    const int la_c = (threadIdx.x & 3) * 4;
    const int lb_r = threadIdx.x >> 4;
    const int lb_c = (threadIdx.x & 15) * 4;
    float acc[4][4] = {};
    for (int k0 = 0; k0 < DD; k0 += 16) {
        float4 av = *(const float4*)&A[(m0 + la_r) * DD + k0 + la_c];
        As[la_c + 0][la_r] = av.x; As[la_c + 1][la_r] = av.y;
        As[la_c + 2][la_r] = av.z; As[la_c + 3][la_r] = av.w;
        *(float4*)&Bs[lb_r][lb_c] = *(const float4*)&W[(k0 + lb_r) * DD + n0 + lb_c];
        __syncthreads();
#pragma unroll
        for (int kk = 0; kk < 16; kk++) {
            float a[4], b[4];
#pragma unroll
            for (int x = 0; x < 4; x++) a[x] = As[kk][ty * 4 + x];
#pragma unroll
            for (int x = 0; x < 4; x++) b[x] = Bs[kk][tx * 4 + x];
#pragma unroll
            for (int i = 0; i < 4; i++)
#pragma unroll
                for (int j = 0; j < 4; j++) acc[i][j] += a[i] * b[j];
        }
        __syncthreads();
    }
#pragma unroll
    for (int i = 0; i < 4; i++) {
        int m = m0 + ty * 4 + i;
#pragma unroll
        for (int j = 0; j < 4; j++) {
            int n = n0 + tx * 4 + j;
            float val = acc[i][j] + (bias ? bias[n] : 0.f);
            if (out0) out0[m * DD + n] = val + (ex0 ? ex0[n] : 0.f);
            if (out1) out1[m * DD + n] = val + (ex1 ? ex1[n] : 0.f);
        }
    }
}

// ---------------- kernel 2: batched score GEMM (K=64 fully resident) -----------
__global__ void score_kernel(const float* __restrict__ Qm, const float* __restrict__ Km,
                             float* __restrict__ Out)
{
    __shared__ float As[64][65];   // As[d][i]
    __shared__ float Bs[64][65];   // Bs[d][j]
    const int z = blockIdx.z, b = z >> 3, h = z & 7;
    const int i0 = blockIdx.y * 64, j0 = blockIdx.x * 64;
    const int tx = threadIdx.x & 15, ty = threadIdx.x >> 4;
    const int lr = threadIdx.x >> 4;
    const int lc = (threadIdx.x & 15) * 4;
    const float* Qb = Qm + (b * SS) * DD + h * DHH;
    const float* Kb = Km + (b * SS) * DD + h * DHH;
#pragma unroll
    for (int p = 0; p < 4; p++) {
        int r = lr + p * 16;
        float4 av = *(const float4*)&Qb[(i0 + r) * DD + lc];
        As[lc + 0][r] = av.x; As[lc + 1][r] = av.y; As[lc + 2][r] = av.z; As[lc + 3][r] = av.w;
        float4 bv = *(const float4*)&Kb[(j0 + r) * DD + lc];
        Bs[lc + 0][r] = bv.x; Bs[lc + 1][r] = bv.y; Bs[lc + 2][r] = bv.z; Bs[lc + 3][r] = bv.w;
    }
    __syncthreads();
    float acc[4][4] = {};
#pragma unroll
    for (int kk = 0; kk < 64; kk++) {
        float a[4], b[4];
#pragma unroll
        for (int x = 0; x < 4; x++) a[x] = As[kk][ty * 4 + x];
#pragma unroll
        for (int x = 0; x < 4; x++) b[x] = Bs[kk][tx * 4 + x];
#pragma unroll
        for (int i = 0; i < 4; i++)
#pragma unroll
            for (int j = 0; j < 4; j++) acc[i][j] += a[i] * b[j];
    }
#pragma unroll
    for (int i = 0; i < 4; i++)
#pragma unroll
        for (int j = 0; j < 4; j++)
            Out[(z * SS + i0 + ty * 4 + i) * SS + j0 + tx * 4 + j] = acc[i][j];
}

// ---------------- kernel 3: rel-shift combine + softmax ------------------------
__global__ void softmax_kernel(float* __restrict__ C, const float* __restrict__ M)
{
    const int row = blockIdx.x;            // (b*H+h)*S + i
    const int i = row & (SS - 1);
    const int base = row * SS;
    const int t = threadIdx.x;
    const float scale = 0.04419417382415922f;  // 1/sqrt(512)

    float sv[4];
    float mx = -1e30f;
#pragma unroll
    for (int q = 0; q < 4; q++) {
        int j = t + q * 256;
        float pv;
        if (j <= i)          pv = M[base + (SS - 1 - i + j)];
        else if (j == i + 1) pv = 0.f;
        else                 pv = M[base + SS + (j - i - 2)];   // row i+1 (wrap artifact)
        float s = (C[base + j] + pv) * scale;
        sv[q] = s;
        mx = fmaxf(mx, s);
    }
    __shared__ float red[8];
    const int lane = t & 31, wid = t >> 5;
#pragma unroll
    for (int o = 16; o > 0; o >>= 1) mx = fmaxf(mx, __shfl_xor_sync(0xffffffffu, mx, o));
    if (lane == 0) red[wid] = mx;
    __syncthreads();
    float rmax = red[0];
#pragma unroll
    for (int w = 1; w < 8; w++) rmax = fmaxf(rmax, red[w]);

    float sum = 0.f;
#pragma unroll
    for (int q = 0; q < 4; q++) { sv[q] = __expf(sv[q] - rmax); sum += sv[q]; }
#pragma unroll
    for (int o = 16; o > 0; o >>= 1) sum += __shfl_xor_sync(0xffffffffu, sum, o);
    __syncthreads();
    if (lane == 0) red[wid] = sum;
    __syncthreads();
    float rsum = 0.f;
#pragma unroll
    for (int w = 0; w < 8; w++) rsum += red[w];
    float inv = 1.f / rsum;
#pragma unroll
    for (int q = 0; q < 4; q++) C[base + t + q * 256] = sv[q] * inv;
}

// ---------------- kernel 4: PV batched GEMM ------------------------------------
__global__ void pv_kernel(const float* __restrict__ Att, const float* __restrict__ V,
                          float* __restrict__ Ctx)
{
    __shared__ float As[32][65];   // As[k][i]
    __shared__ float Bs[32][64];   // Bs[k][d]
    const int z = blockIdx.z, b = z >> 3, h = z & 7;
    const int i0 = blockIdx.y * 64;
    const int tx = threadIdx.x & 15, ty = threadIdx.x >> 4;
    const float* Ab = Att + (z * SS) * SS;
    const float* Vb = V + (b * SS) * DD + h * DHH;
    float acc[4][4] = {};
    for (int k0 = 0; k0 < SS; k0 += 32) {
#pragma unroll
        for (int p = 0; p < 2; p++) {
            int r = (threadIdx.x >> 3) + p * 32;
            int c = (threadIdx.x & 7) * 4;
            float4 av = *(const float4*)&Ab[(i0 + r) * SS + k0 + c];
            As[c + 0][r] = av.x; As[c + 1][r] = av.y; As[c + 2][r] = av.z; As[c + 3][r] = av.w;
        }
#pragma unroll
        for (int p = 0; p < 2; p++) {
            int r = (threadIdx.x >> 4) + p * 16;
            int c = (threadIdx.x & 15) * 4;
            *(float4*)&Bs[r][c] = *(const float4*)&Vb[(k0 + r) * DD + c];
        }
        __syncthreads();
#pragma unroll
        for (int kk = 0; kk < 32; kk++) {
            float a[4], b[4];
#pragma unroll
            for (int x = 0; x < 4; x++) a[x] = As[kk][ty * 4 + x];
#pragma unroll
            for (int x = 0; x < 4; x++) b[x] = Bs[kk][tx * 4 + x];
#pragma unroll
            for (int i = 0; i < 4; i++)
#pragma unroll
                for (int j = 0; j < 4; j++) acc[i][j] += a[i] * b[j];
        }
        __syncthreads();
    }
#pragma unroll
    for (int i = 0; i < 4; i++)
#pragma unroll
        for (int j = 0; j < 4; j++)
            Ctx[(b * SS + i0 + ty * 4 + i) * DD + h * DHH + tx * 4 + j] = acc[i][j];
}

// ---------------- launcher ------------------------------------------------------
extern "C" void kernel_launch(void* const* d_in, const int* in_sizes, int n_in,
                              void* d_out, int out_size)
{
    (void)in_sizes; (void)n_in; (void)out_size;
    const float* query = (const float*)d_in[0];
    const float* key   = (const float*)d_in[1];
    const float* value = (const float*)d_in[2];
    const float* pose  = (const float*)d_in[3];
    const float* Wq = (const float*)d_in[4];
    const float* bq = (const float*)d_in[5];
    const float* Wk = (const float*)d_in[6];
    const float* bk = (const float*)d_in[7];
    const float* Wv = (const float*)d_in[8];
    const float* bv = (const float*)d_in[9];
    const float* Wp = (const float*)d_in[10];
    const float* ub = (const float*)d_in[11];   // u_bias [H*DH] flat = per-column
    const float* vb = (const float*)d_in[12];   // v_bias
    const float* Wo = (const float*)d_in[13];
    const float* bo = (const float*)d_in[14];
    float* out = (float*)d_out;

    float *qu, *qv, *kk, *vv, *pp, *C, *M, *ctx;
    cudaGetSymbolAddress((void**)&qu,  g_qu);
    cudaGetSymbolAddress((void**)&qv,  g_qv);
    cudaGetSymbolAddress((void**)&kk,  g_k);
    cudaGetSymbolAddress((void**)&vv,  g_v);
    cudaGetSymbolAddress((void**)&pp,  g_p);
    cudaGetSymbolAddress((void**)&C,   g_C);
    cudaGetSymbolAddress((void**)&M,   g_M);
    cudaGetSymbolAddress((void**)&ctx, g_ctx);

    dim3 pg(DD / 64, MTOT / 64);   // (8, 128)
    proj_kernel<<<pg, 256>>>(query, Wq, bq, qu, ub, qv, vb);
    proj_kernel<<<pg, 256>>>(key,   Wk, bk, kk, nullptr, nullptr, nullptr);
    proj_kernel<<<pg, 256>>>(value, Wv, bv, vv, nullptr, nullptr, nullptr);
    proj_kernel<<<pg, 256>>>(pose,  Wp, nullptr, pp, nullptr, nullptr, nullptr);

    dim3 sg(SS / 64, SS / 64, BH); // (16,16,64)
    score_kernel<<<sg, 256>>>(qu, kk, C);
    score_kernel<<<sg, 256>>>(qv, pp, M);

    softmax_kernel<<<BH * SS, 256>>>(C, M);

    dim3 vg(1, SS / 64, BH);
    pv_kernel<<<vg, 256>>>(C, vv, ctx);

    proj_kernel<<<pg, 256>>>(ctx, Wo, bo, out, nullptr, nullptr, nullptr);
}

// round 2
// speedup vs baseline: 1.4198x; 1.4198x over previous
#include <cuda_runtime.h>
#include <cstdint>

#define BB 8
#define SS 1024
#define DD 512
#define HH 8
#define DHH 64
#define MTOT (BB*SS)   // 8192
#define BH   (BB*HH)   // 64

// ---------------- scratch (__device__ globals) ---------------------------------
__device__ float g_qu[MTOT*DD];
__device__ float g_qv[MTOT*DD];
__device__ float g_k [MTOT*DD];
__device__ float g_v [MTOT*DD];
__device__ float g_p [MTOT*DD];
__device__ float g_C [BH*SS*SS];                // content scores -> attention
__device__ float g_M [BH*SS*SS];                // pos scores pre-shift
__device__ float g_ctx[MTOT*DD];

// ---------------- tf32 helpers -------------------------------------------------
__device__ __forceinline__ uint32_t f2tf(float x) {
    uint32_t r;
    asm("cvt.rna.tf32.f32 %0, %1;" : "=r"(r) : "f"(x));
    return r;
}

__device__ __forceinline__ void mma_tf32(float c[4],
                                         uint32_t a0, uint32_t a1, uint32_t a2, uint32_t a3,
                                         uint32_t b0, uint32_t b1)
{
    asm volatile(
        "mma.sync.aligned.m16n8k8.row.col.f32.tf32.tf32.f32 "
        "{%0,%1,%2,%3}, {%4,%5,%6,%7}, {%8,%9}, {%0,%1,%2,%3};"
        : "+f"(c[0]), "+f"(c[1]), "+f"(c[2]), "+f"(c[3])
        : "r"(a0), "r"(a1), "r"(a2), "r"(a3), "r"(b0), "r"(b1));
}

// ---------------- kernel 1: projection GEMM (tf32 MMA) -------------------------
// C[8192,512] = A[8192,512] @ W[512,512].  Tile 128x64, K-step 32.
// 256 thr = 8 warps, warp tile 32x32 (2 m-atoms x 4 n-atoms).
__global__ void proj_kernel(const float* __restrict__ A, const float* __restrict__ W,
                            const float* __restrict__ bias,
                            float* __restrict__ out0, const float* __restrict__ ex0,
                            float* __restrict__ out1, const float* __restrict__ ex1)
{
    __shared__ uint32_t As[32][132];   // As[k][m]
    __shared__ uint32_t Bs[32][68];    // Bs[k][n]
    const int tid  = threadIdx.x;
    const int lane = tid & 31, w = tid >> 5;
    const int wm = w & 3, wn = w >> 2;        // 4 x 2 warps
    const int m_w = wm * 32, n_w = wn * 32;
    const int m0 = blockIdx.y * 128, n0 = blockIdx.x * 64;
    const int lq = lane >> 2, lr = lane & 3;  // lq=0..7, lr=0..3

    float acc[2][4][4] = {};

    for (int k0 = 0; k0 < DD; k0 += 32) {
        // load A tile 128x32 -> As[k][m]  (4 float4 / thread)
#pragma unroll
        for (int t = 0; t < 4; t++) {
            int id = tid + t * 256;           // 0..1023
            int row = id >> 3;                // 0..127
            int c4  = (id & 7) * 4;           // 0..28
            float4 av = *(const float4*)&A[(m0 + row) * DD + k0 + c4];
            As[c4 + 0][row] = f2tf(av.x); As[c4 + 1][row] = f2tf(av.y);
            As[c4 + 2][row] = f2tf(av.z); As[c4 + 3][row] = f2tf(av.w);
        }
        // load W tile 32x64 -> Bs[k][n]  (2 float4 / thread)
#pragma unroll
        for (int t = 0; t < 2; t++) {
            int id = tid + t * 256;           // 0..511
            int row = id >> 4;                // 0..31
            int c4  = (id & 15) * 4;          // 0..60
            float4 bv = *(const float4*)&W[(k0 + row) * DD + n0 + c4];
            Bs[row][c4 + 0] = f2tf(bv.x); Bs[row][c4 + 1] = f2tf(bv.y);
            Bs[row][c4 + 2] = f2tf(bv.z); Bs[row][c4 + 3] = f2tf(bv.w);
        }
        __syncthreads();
#pragma unroll
        for (int kk = 0; kk < 32; kk += 8) {
            uint32_t a[2][4], b[4][2];
#pragma unroll
            for (int am = 0; am < 2; am++) {
                int mb = m_w + am * 16;
                a[am][0] = As[kk + lr][mb + lq];
                a[am][1] = As[kk + lr][mb + 8 + lq];
                a[am][2] = As[kk + 4 + lr][mb + lq];
                a[am][3] = As[kk + 4 + lr][mb + 8 + lq];
            }
#pragma unroll
            for (int an = 0; an < 4; an++) {
                int nb = n_w + an * 8;
                b[an][0] = Bs[kk + lr][nb + lq];
                b[an][1] = Bs[kk + 4 + lr][nb + lq];
            }
#pragma unroll
            for (int am = 0; am < 2; am++)
#pragma unroll
                for (int an = 0; an < 4; an++)
                    mma_tf32(acc[am][an], a[am][0], a[am][1], a[am][2], a[am][3],
                             b[an][0], b[an][1]);
        }
        __syncthreads();
    }
#pragma unroll
    for (int am = 0; am < 2; am++) {
#pragma unroll
        for (int an = 0; an < 4; an++) {
#pragma unroll
            for (int half = 0; half < 2; half++) {
                int row = m0 + m_w + am * 16 + lq + half * 8;
                int col = n0 + n_w + an * 8 + lr * 2;
                float v0 = acc[am][an][half * 2 + 0];
                float v1 = acc[am][an][half * 2 + 1];
                if (bias) { v0 += bias[col]; v1 += bias[col + 1]; }
                if (out0) {
                    float e0 = ex0 ? ex0[col] : 0.f, e1 = ex0 ? ex0[col + 1] : 0.f;
                    out0[row * DD + col]     = v0 + e0;
                    out0[row * DD + col + 1] = v1 + e1;
                }
                if (out1) {
                    float e0 = ex1 ? ex1[col] : 0.f, e1 = ex1 ? ex1[col + 1] : 0.f;
                    out1[row * DD + col]     = v0 + e0;
                    out1[row * DD + col + 1] = v1 + e1;
                }
            }
        }
    }
}

// ---------------- kernel 2: batched score GEMM (tf32 MMA) ----------------------
// Out[z,i,j] = sum_d Q[b,i,h*64+d] * K[b,j,h*64+d].  Tile 64x64, K(dim)=64.
// 256 thr = 8 warps, warp tile 16x32 (1 m-atom x 4 n-atoms), 4x2 warp grid.
__global__ void score_kernel(const float* __restrict__ Qm, const float* __restrict__ Km,
                             float* __restrict__ Out)
{
    __shared__ uint32_t Qs[64][68];    // Qs[d][i]
    __shared__ uint32_t Ks[64][68];    // Ks[d][j]
    const int tid  = threadIdx.x;
    const int lane = tid & 31, w = tid >> 5;
    const int wm = w & 3, wn = w >> 2;        // 4 x 2
    const int m_w = wm * 16, n_w = wn * 32;
    const int z = blockIdx.z, b = z >> 3, h = z & 7;
    const int i0 = blockIdx.y * 64, j0 = blockIdx.x * 64;
    const int lq = lane >> 2, lr = lane & 3;
    const float* Qb = Qm + (size_t)(b * SS) * DD + h * DHH;
    const float* Kb = Km + (size_t)(b * SS) * DD + h * DHH;

    // load 64x64 Q and K tiles, transposed into [d][row]
#pragma unroll
    for (int t = 0; t < 4; t++) {
        int id = tid + t * 256;              // 0..1023
        int row = id >> 4;                   // 0..63
        int c4  = (id & 15) * 4;             // 0..60
        float4 qv = *(const float4*)&Qb[(i0 + row) * DD + c4];
        Qs[c4 + 0][row] = f2tf(qv.x); Qs[c4 + 1][row] = f2tf(qv.y);
        Qs[c4 + 2][row] = f2tf(qv.z); Qs[c4 + 3][row] = f2tf(qv.w);
        float4 kv = *(const float4*)&Kb[(j0 + row) * DD + c4];
        Ks[c4 + 0][row] = f2tf(kv.x); Ks[c4 + 1][row] = f2tf(kv.y);
        Ks[c4 + 2][row] = f2tf(kv.z); Ks[c4 + 3][row] = f2tf(kv.w);
    }
    __syncthreads();

    float acc[4][4] = {};
#pragma unroll
    for (int kk = 0; kk < 64; kk += 8) {
        uint32_t a[4], b2[4][2];
        a[0] = Qs[kk + lr][m_w + lq];
        a[1] = Qs[kk + lr][m_w + 8 + lq];
        a[2] = Qs[kk + 4 + lr][m_w + lq];
        a[3] = Qs[kk + 4 + lr][m_w + 8 + lq];
#pragma unroll
        for (int an = 0; an < 4; an++) {
            int nb = n_w + an * 8;
            b2[an][0] = Ks[kk + lr][nb + lq];
            b2[an][1] = Ks[kk + 4 + lr][nb + lq];
        }
#pragma unroll
        for (int an = 0; an < 4; an++)
            mma_tf32(acc[an], a[0], a[1], a[2], a[3], b2[an][0], b2[an][1]);
    }

    float* Ob = Out + ((size_t)z * SS + i0) * SS + j0;
#pragma unroll
    for (int an = 0; an < 4; an++) {
#pragma unroll
        for (int half = 0; half < 2; half++) {
            int row = m_w + lq + half * 8;
            int col = n_w + an * 8 + lr * 2;
            float2 vv = make_float2(acc[an][half * 2 + 0], acc[an][half * 2 + 1]);
            *(float2*)&Ob[(size_t)row * SS + col] = vv;
        }
    }
}

// ---------------- kernel 3: rel-shift combine + softmax ------------------------
__global__ void softmax_kernel(float* __restrict__ C, const float* __restrict__ M)
{
    const int row = blockIdx.x;            // (b*H+h)*S + i
    const int i = row & (SS - 1);
    const size_t base = (size_t)row * SS;
    const int t = threadIdx.x;
    const float scale = 0.04419417382415922f;  // 1/sqrt(512)

    float sv[4];
    float mx = -1e30f;
#pragma unroll
    for (int q = 0; q < 4; q++) {
        int j = t + q * 256;
        float pv;
        if (j <= i)          pv = M[base + (SS - 1 - i + j)];
        else if (j == i + 1) pv = 0.f;
        else                 pv = M[base + SS + (j - i - 2)];   // wrap artifact row i+1
        float s = (C[base + j] + pv) * scale;
        sv[q] = s;
        mx = fmaxf(mx, s);
    }
    __shared__ float red[8];
    const int lane = t & 31, wid = t >> 5;
#pragma unroll
    for (int o = 16; o > 0; o >>= 1) mx = fmaxf(mx, __shfl_xor_sync(0xffffffffu, mx, o));
    if (lane == 0) red[wid] = mx;
    __syncthreads();
    float rmax = red[0];
#pragma unroll
    for (int wv = 1; wv < 8; wv++) rmax = fmaxf(rmax, red[wv]);

    float sum = 0.f;
#pragma unroll
    for (int q = 0; q < 4; q++) { sv[q] = __expf(sv[q] - rmax); sum += sv[q]; }
#pragma unroll
    for (int o = 16; o > 0; o >>= 1) sum += __shfl_xor_sync(0xffffffffu, sum, o);
    __syncthreads();
    if (lane == 0) red[wid] = sum;
    __syncthreads();
    float rsum = 0.f;
#pragma unroll
    for (int wv = 0; wv < 8; wv++) rsum += red[wv];
    float inv = 1.f / rsum;
#pragma unroll
    for (int q = 0; q < 4; q++) C[base + t + q * 256] = sv[q] * inv;
}

// ---------------- kernel 4: PV batched GEMM (tf32 MMA) -------------------------
// Ctx[b,i,h*64+d] = sum_j Att[z,i,j] * V[b,j,h*64+d].  Tile 64(i)x64(d), K-step 32.
__global__ void pv_kernel(const float* __restrict__ Att, const float* __restrict__ V,
                          float* __restrict__ Ctx)
{
    __shared__ uint32_t As[32][68];    // As[j][i]
    __shared__ uint32_t Bs[32][68];    // Bs[j][d]
    const int tid  = threadIdx.x;
    const int lane = tid & 31, w = tid >> 5;
    const int wm = w & 3, wn = w >> 2;
    const int m_w = wm * 16, n_w = wn * 32;
    const int z = blockIdx.z, b = z >> 3, h = z & 7;
    const int i0 = blockIdx.y * 64;
    const int lq = lane >> 2, lr = lane & 3;
    const float* Ab = Att + (size_t)z * SS * SS;
    const float* Vb = V + (size_t)(b * SS) * DD + h * DHH;

    float acc[4][4] = {};
    for (int k0 = 0; k0 < SS; k0 += 32) {
        // Att tile 64(i) x 32(j)  (2 float4 / thread)
#pragma unroll
        for (int t = 0; t < 2; t++) {
            int id = tid + t * 256;          // 0..511
            int row = id >> 3;               // 0..63
            int c4  = (id & 7) * 4;          // 0..28
            float4 av = *(const float4*)&Ab[(size_t)(i0 + row) * SS + k0 + c4];
            As[c4 + 0][row] = f2tf(av.x); As[c4 + 1][row] = f2tf(av.y);
            As[c4 + 2][row] = f2tf(av.z); As[c4 + 3][row] = f2tf(av.w);
        }
        // V tile 32(j) x 64(d)
#pragma unroll
        for (int t = 0; t < 2; t++) {
            int id = tid + t * 256;
            int row = id >> 4;               // 0..31
            int c4  = (id & 15) * 4;         // 0..60
            float4 bv = *(const float4*)&Vb[(size_t)(k0 + row) * DD + c4];
            Bs[row][c4 + 0] = f2tf(bv.x); Bs[row][c4 + 1] = f2tf(bv.y);
            Bs[row][c4 + 2] = f2tf(bv.z); Bs[row][c4 + 3] = f2tf(bv.w);
        }
        __syncthreads();
#pragma unroll
        for (int kk = 0; kk < 32; kk += 8) {
            uint32_t a[4], b2[4][2];
            a[0] = As[kk + lr][m_w + lq];
            a[1] = As[kk + lr][m_w + 8 + lq];
            a[2] = As[kk + 4 + lr][m_w + lq];
            a[3] = As[kk + 4 + lr][m_w + 8 + lq];
#pragma unroll
            for (int an = 0; an < 4; an++) {
                int nb = n_w + an * 8;
                b2[an][0] = Bs[kk + lr][nb + lq];
                b2[an][1] = Bs[kk + 4 + lr][nb + lq];
            }
#pragma unroll
            for (int an = 0; an < 4; an++)
                mma_tf32(acc[an], a[0], a[1], a[2], a[3], b2[an][0], b2[an][1]);
        }
        __syncthreads();
    }
#pragma unroll
    for (int an = 0; an < 4; an++) {
#pragma unroll
        for (int half = 0; half < 2; half++) {
            int row = i0 + m_w + lq + half * 8;
            int col = n_w + an * 8 + lr * 2;
            float2 vv = make_float2(acc[an][half * 2 + 0], acc[an][half * 2 + 1]);
            *(float2*)&Ctx[(size_t)(b * SS + row) * DD + h * DHH + col] = vv;
        }
    }
}

// ---------------- launcher ------------------------------------------------------
extern "C" void kernel_launch(void* const* d_in, const int* in_sizes, int n_in,
                              void* d_out, int out_size)
{
    (void)in_sizes; (void)n_in; (void)out_size;
    const float* query = (const float*)d_in[0];
    const float* key   = (const float*)d_in[1];
    const float* value = (const float*)d_in[2];
    const float* pose  = (const float*)d_in[3];
    const float* Wq = (const float*)d_in[4];
    const float* bq = (const float*)d_in[5];
    const float* Wk = (const float*)d_in[6];
    const float* bk = (const float*)d_in[7];
    const float* Wv = (const float*)d_in[8];
    const float* bv = (const float*)d_in[9];
    const float* Wp = (const float*)d_in[10];
    const float* ub = (const float*)d_in[11];
    const float* vb = (const float*)d_in[12];
    const float* Wo = (const float*)d_in[13];
    const float* bo = (const float*)d_in[14];
    float* out = (float*)d_out;

    float *qu, *qv, *kk, *vv, *pp, *C, *M, *ctx;
    cudaGetSymbolAddress((void**)&qu,  g_qu);
    cudaGetSymbolAddress((void**)&qv,  g_qv);
    cudaGetSymbolAddress((void**)&kk,  g_k);
    cudaGetSymbolAddress((void**)&vv,  g_v);
    cudaGetSymbolAddress((void**)&pp,  g_p);
    cudaGetSymbolAddress((void**)&C,   g_C);
    cudaGetSymbolAddress((void**)&M,   g_M);
    cudaGetSymbolAddress((void**)&ctx, g_ctx);

    dim3 pg(DD / 64, MTOT / 128);          // (8, 64)
    proj_kernel<<<pg, 256>>>(query, Wq, bq, qu, ub, qv, vb);
    proj_kernel<<<pg, 256>>>(key,   Wk, bk, kk, nullptr, nullptr, nullptr);
    proj_kernel<<<pg, 256>>>(value, Wv, bv, vv, nullptr, nullptr, nullptr);
    proj_kernel<<<pg, 256>>>(pose,  Wp, nullptr, pp, nullptr, nullptr, nullptr);

    dim3 sg(SS / 64, SS / 64, BH);         // (16,16,64)
    score_kernel<<<sg, 256>>>(qu, kk, C);
    score_kernel<<<sg, 256>>>(qv, pp, M);

    softmax_kernel<<<BH * SS, 256>>>(C, M);

    dim3 vg(1, SS / 64, BH);               // (1,16,64)
    pv_kernel<<<vg, 256>>>(C, vv, ctx);

    proj_kernel<<<pg, 256>>>(ctx, Wo, bo, out, nullptr, nullptr, nullptr);
}

// round 3
// speedup vs baseline: 1.6434x; 1.1575x over previous
#include <cuda_runtime.h>
#include <cstdint>

#define BB 8
#define SS 1024
#define DD 512
#define HH 8
#define DHH 64
#define MTOT (BB*SS)   // 8192
#define BH   (BB*HH)   // 64

// ---------------- scratch (__device__ globals) ---------------------------------
__device__ float g_qu[MTOT*DD];
__device__ float g_qv[MTOT*DD];
__device__ float g_k [MTOT*DD];
__device__ float g_v [MTOT*DD];
__device__ float g_p [MTOT*DD];
__device__ float g_C [BH*SS*SS];                // content scores (raw)
__device__ float g_M [BH*SS*SS];                // pos scores pre-shift
__device__ float g_ctx[MTOT*DD];

// ---------------- tf32 helpers -------------------------------------------------
__device__ __forceinline__ uint32_t f2tf(float x) {
    uint32_t r;
    asm("cvt.rna.tf32.f32 %0, %1;" : "=r"(r) : "f"(x));
    return r;
}

__device__ __forceinline__ void mma_tf32(float c[4],
                                         uint32_t a0, uint32_t a1, uint32_t a2, uint32_t a3,
                                         uint32_t b0, uint32_t b1)
{
    asm volatile(
        "mma.sync.aligned.m16n8k8.row.col.f32.tf32.tf32.f32 "
        "{%0,%1,%2,%3}, {%4,%5,%6,%7}, {%8,%9}, {%0,%1,%2,%3};"
        : "+f"(c[0]), "+f"(c[1]), "+f"(c[2]), "+f"(c[3])
        : "r"(a0), "r"(a1), "r"(a2), "r"(a3), "r"(b0), "r"(b1));
}

// ---------------- kernel 1: projection GEMM v2 ---------------------------------
// C[8192,512] = A[8192,512] @ W[512,512]. Block tile 128x128, K-step 16.
// 256 thr = 8 warps in 2(m) x 4(n); warp tile 64x32 (4 m-atoms x 4 n-atoms).
// Register double-buffer: prefetch next K-slab from gmem during the MMA loop.
__global__ void __launch_bounds__(256, 2)
proj_kernel(const float* __restrict__ A, const float* __restrict__ W,
            const float* __restrict__ bias,
            float* __restrict__ out0, const float* __restrict__ ex0,
            float* __restrict__ out1, const float* __restrict__ ex1)
{
    __shared__ uint32_t As[16][132];   // As[k][m]
    __shared__ uint32_t Bs[16][132];   // Bs[k][n]
    const int tid  = threadIdx.x;
    const int lane = tid & 31, w = tid >> 5;
    const int wm = w & 1, wn = w >> 1;            // 2 x 4
    const int m_w = wm * 64, n_w = wn * 32;
    const int m0 = blockIdx.y * 128, n0 = blockIdx.x * 128;
    const int lq = lane >> 2, lr = lane & 3;

    // load index mapping
    const int a_row = tid >> 2;                    // 0..63  (t adds 64)
    const int a_c4  = (tid & 3) * 4;               // 0..12
    const int b_row = tid >> 5;                    // 0..7   (t adds 8)
    const int b_c4  = (tid & 31) * 4;              // 0..124

    float4 pa[2], pb[2];
#pragma unroll
    for (int t = 0; t < 2; t++)
        pa[t] = *(const float4*)&A[(m0 + a_row + t * 64) * DD + a_c4];
#pragma unroll
    for (int t = 0; t < 2; t++)
        pb[t] = *(const float4*)&W[(b_row + t * 8) * DD + n0 + b_c4];

    float acc[4][4][4] = {};

    for (int k0 = 0; k0 < DD; k0 += 16) {
        // store current slab to smem (with tf32 convert)
#pragma unroll
        for (int t = 0; t < 2; t++) {
            int row = a_row + t * 64;
            As[a_c4 + 0][row] = f2tf(pa[t].x); As[a_c4 + 1][row] = f2tf(pa[t].y);
            As[a_c4 + 2][row] = f2tf(pa[t].z); As[a_c4 + 3][row] = f2tf(pa[t].w);
        }
#pragma unroll
        for (int t = 0; t < 2; t++) {
            int row = b_row + t * 8;
            Bs[row][b_c4 + 0] = f2tf(pb[t].x); Bs[row][b_c4 + 1] = f2tf(pb[t].y);
            Bs[row][b_c4 + 2] = f2tf(pb[t].z); Bs[row][b_c4 + 3] = f2tf(pb[t].w);
        }
        __syncthreads();
        // prefetch next slab (overlaps MMA below)
        if (k0 + 16 < DD) {
#pragma unroll
            for (int t = 0; t < 2; t++)
                pa[t] = *(const float4*)&A[(m0 + a_row + t * 64) * DD + k0 + 16 + a_c4];
#pragma unroll
            for (int t = 0; t < 2; t++)
                pb[t] = *(const float4*)&W[(k0 + 16 + b_row + t * 8) * DD + n0 + b_c4];
        }
#pragma unroll
        for (int kk = 0; kk < 16; kk += 8) {
            uint32_t a[4][4], b[4][2];
#pragma unroll
            for (int am = 0; am < 4; am++) {
                int mb = m_w + am * 16;
                a[am][0] = As[kk + lr][mb + lq];
                a[am][1] = As[kk + lr][mb + 8 + lq];
                a[am][2] = As[kk + 4 + lr][mb + lq];
                a[am][3] = As[kk + 4 + lr][mb + 8 + lq];
            }
#pragma unroll
            for (int an = 0; an < 4; an++) {
                int nb = n_w + an * 8;
                b[an][0] = Bs[kk + lr][nb + lq];
                b[an][1] = Bs[kk + 4 + lr][nb + lq];
            }
#pragma unroll
            for (int am = 0; am < 4; am++)
#pragma unroll
                for (int an = 0; an < 4; an++)
                    mma_tf32(acc[am][an], a[am][0], a[am][1], a[am][2], a[am][3],
                             b[an][0], b[an][1]);
        }
        __syncthreads();
    }

#pragma unroll
    for (int am = 0; am < 4; am++) {
#pragma unroll
        for (int an = 0; an < 4; an++) {
#pragma unroll
            for (int half = 0; half < 2; half++) {
                int row = m0 + m_w + am * 16 + lq + half * 8;
                int col = n0 + n_w + an * 8 + lr * 2;
                float v0 = acc[am][an][half * 2 + 0];
                float v1 = acc[am][an][half * 2 + 1];
                if (bias) { v0 += bias[col]; v1 += bias[col + 1]; }
                if (out0) {
                    float e0 = ex0 ? ex0[col] : 0.f, e1 = ex0 ? ex0[col + 1] : 0.f;
                    float2 vv = make_float2(v0 + e0, v1 + e1);
                    *(float2*)&out0[(size_t)row * DD + col] = vv;
                }
                if (out1) {
                    float e0 = ex1 ? ex1[col] : 0.f, e1 = ex1 ? ex1[col + 1] : 0.f;
                    float2 vv = make_float2(v0 + e0, v1 + e1);
                    *(float2*)&out1[(size_t)row * DD + col] = vv;
                }
            }
        }
    }
}

// ---------------- kernel 2: batched score GEMM (tf32 MMA) ----------------------
__global__ void score_kernel(const float* __restrict__ Qm, const float* __restrict__ Km,
                             float* __restrict__ Out)
{
    __shared__ uint32_t Qs[64][68];
    __shared__ uint32_t Ks[64][68];
    const int tid  = threadIdx.x;
    const int lane = tid & 31, w = tid >> 5;
    const int wm = w & 3, wn = w >> 2;
    const int m_w = wm * 16, n_w = wn * 32;
    const int z = blockIdx.z, b = z >> 3, h = z & 7;
    const int i0 = blockIdx.y * 64, j0 = blockIdx.x * 64;
    const int lq = lane >> 2, lr = lane & 3;
    const float* Qb = Qm + (size_t)(b * SS) * DD + h * DHH;
    const float* Kb = Km + (size_t)(b * SS) * DD + h * DHH;

#pragma unroll
    for (int t = 0; t < 4; t++) {
        int id = tid + t * 256;
        int row = id >> 4;
        int c4  = (id & 15) * 4;
        float4 qv = *(const float4*)&Qb[(i0 + row) * DD + c4];
        Qs[c4 + 0][row] = f2tf(qv.x); Qs[c4 + 1][row] = f2tf(qv.y);
        Qs[c4 + 2][row] = f2tf(qv.z); Qs[c4 + 3][row] = f2tf(qv.w);
        float4 kv = *(const float4*)&Kb[(j0 + row) * DD + c4];
        Ks[c4 + 0][row] = f2tf(kv.x); Ks[c4 + 1][row] = f2tf(kv.y);
        Ks[c4 + 2][row] = f2tf(kv.z); Ks[c4 + 3][row] = f2tf(kv.w);
    }
    __syncthreads();

    float acc[4][4] = {};
#pragma unroll
    for (int kk = 0; kk < 64; kk += 8) {
        uint32_t a[4], b2[4][2];
        a[0] = Qs[kk + lr][m_w + lq];
        a[1] = Qs[kk + lr][m_w + 8 + lq];
        a[2] = Qs[kk + 4 + lr][m_w + lq];
        a[3] = Qs[kk + 4 + lr][m_w + 8 + lq];
#pragma unroll
        for (int an = 0; an < 4; an++) {
            int nb = n_w + an * 8;
            b2[an][0] = Ks[kk + lr][nb + lq];
            b2[an][1] = Ks[kk + 4 + lr][nb + lq];
        }
#pragma unroll
        for (int an = 0; an < 4; an++)
            mma_tf32(acc[an], a[0], a[1], a[2], a[3], b2[an][0], b2[an][1]);
    }

    float* Ob = Out + ((size_t)z * SS + i0) * SS + j0;
#pragma unroll
    for (int an = 0; an < 4; an++) {
#pragma unroll
        for (int half = 0; half < 2; half++) {
            int row = m_w + lq + half * 8;
            int col = n_w + an * 8 + lr * 2;
            float2 vv = make_float2(acc[an][half * 2 + 0], acc[an][half * 2 + 1]);
            *(float2*)&Ob[(size_t)row * SS + col] = vv;
        }
    }
}

// ---------------- kernel 3: fused shift + online-softmax + PV ------------------
// grid (S/128, BH), 256 thr = 8 warps; warp w owns 16 q-rows, full 64-wide j tile.
// Online softmax in registers; P routed via per-warp smem into tf32 MMA vs V.
#define FA_SMEM_BYTES ((64*72 + 8*16*68) * 4)
__global__ void __launch_bounds__(256, 2)
fa_kernel(const float* __restrict__ C, const float* __restrict__ M,
          const float* __restrict__ V, float* __restrict__ Ctx)
{
    extern __shared__ uint32_t fa_smem[];
    uint32_t (*Vs)[72] = (uint32_t(*)[72])fa_smem;         // V tile [j][d]
    uint32_t* Ps = fa_smem + 64 * 72;                      // per-warp P [16][68]

    const int tid  = threadIdx.x;
    const int lane = tid & 31, w = tid >> 5;
    const int lq = lane >> 2, lr = lane & 3;
    const int z = blockIdx.y, b = z >> 3, h = z & 7;
    const int i0 = blockIdx.x * 128;
    const int r0 = i0 + w * 16 + lq;       // first row this thread owns
    const int r1 = r0 + 8;                 // second row

    const float* Crow0 = C + ((size_t)z * SS + r0) * SS;
    const float* Crow1 = C + ((size_t)z * SS + r1) * SS;
    const float* Mrow0 = M + ((size_t)z * SS + r0) * SS;
    const float* Mrow1 = M + ((size_t)z * SS + r1) * SS;
    const float* Vb = V + (size_t)(b * SS) * DD + h * DHH;
    uint32_t* Pw = Ps + w * (16 * 68);

    const float scale = 0.04419417382415922f;   // 1/sqrt(512)

    float acc[8][4] = {};
    float rm0 = -1e30f, rm1 = -1e30f, l0 = 0.f, l1 = 0.f;

    for (int j0 = 0; j0 < SS; j0 += 64) {
        __syncthreads();   // prior MMA reads of Vs complete (WAR)
        // cooperative V tile load [64 j x 64 d]
#pragma unroll
        for (int t = 0; t < 4; t++) {
            int id = tid + t * 256;
            int row = id >> 4;
            int c4  = (id & 15) * 4;
            float4 bv = *(const float4*)&Vb[(size_t)(j0 + row) * DD + c4];
            Vs[row][c4 + 0] = f2tf(bv.x); Vs[row][c4 + 1] = f2tf(bv.y);
            Vs[row][c4 + 2] = f2tf(bv.z); Vs[row][c4 + 3] = f2tf(bv.w);
        }

        // scores for this warp's 16 rows x 64 cols
        float p0[8][2], p1[8][2];
        float tm0 = -1e30f, tm1 = -1e30f;
#pragma unroll
        for (int an = 0; an < 8; an++) {
            int jc = j0 + an * 8 + 2 * lr;
            float2 c0 = *(const float2*)&Crow0[jc];
            float2 c1 = *(const float2*)&Crow1[jc];
#pragma unroll
            for (int e = 0; e < 2; e++) {
                int j = jc + e;
                float pv0, pv1;
                if (j <= r0)          pv0 = Mrow0[SS - 1 - r0 + j];
                else if (j == r0 + 1) pv0 = 0.f;
                else                  pv0 = Mrow0[SS + (j - r0 - 2)];
                if (j <= r1)          pv1 = Mrow1[SS - 1 - r1 + j];
                else if (j == r1 + 1) pv1 = 0.f;
                else                  pv1 = Mrow1[SS + (j - r1 - 2)];
                float s0 = ((e ? c0.y : c0.x) + pv0) * scale;
                float s1 = ((e ? c1.y : c1.x) + pv1) * scale;
                p0[an][e] = s0; p1[an][e] = s1;
                tm0 = fmaxf(tm0, s0); tm1 = fmaxf(tm1, s1);
            }
        }
        // row max across the 4 lanes sharing each row
        tm0 = fmaxf(tm0, __shfl_xor_sync(0xffffffffu, tm0, 1));
        tm0 = fmaxf(tm0, __shfl_xor_sync(0xffffffffu, tm0, 2));
        tm1 = fmaxf(tm1, __shfl_xor_sync(0xffffffffu, tm1, 1));
        tm1 = fmaxf(tm1, __shfl_xor_sync(0xffffffffu, tm1, 2));

        float nm0 = fmaxf(rm0, tm0), nm1 = fmaxf(rm1, tm1);
        float al0 = __expf(rm0 - nm0), al1 = __expf(rm1 - nm1);
        float sum0 = 0.f, sum1 = 0.f;
#pragma unroll
        for (int an = 0; an < 8; an++)
#pragma unroll
            for (int e = 0; e < 2; e++) {
                p0[an][e] = __expf(p0[an][e] - nm0); sum0 += p0[an][e];
                p1[an][e] = __expf(p1[an][e] - nm1); sum1 += p1[an][e];
            }
        sum0 += __shfl_xor_sync(0xffffffffu, sum0, 1);
        sum0 += __shfl_xor_sync(0xffffffffu, sum0, 2);
        sum1 += __shfl_xor_sync(0xffffffffu, sum1, 1);
        sum1 += __shfl_xor_sync(0xffffffffu, sum1, 2);
        l0 = l0 * al0 + sum0; l1 = l1 * al1 + sum1;
        rm0 = nm0; rm1 = nm1;

        // rescale O accumulators
#pragma unroll
        for (int an = 0; an < 8; an++) {
            acc[an][0] *= al0; acc[an][1] *= al0;
            acc[an][2] *= al1; acc[an][3] *= al1;
        }
        // write P tile (tf32) to this warp's smem region
#pragma unroll
        for (int an = 0; an < 8; an++) {
            int col = an * 8 + 2 * lr;
            Pw[lq * 68 + col]       = f2tf(p0[an][0]);
            Pw[lq * 68 + col + 1]   = f2tf(p0[an][1]);
            Pw[(lq + 8) * 68 + col]     = f2tf(p1[an][0]);
            Pw[(lq + 8) * 68 + col + 1] = f2tf(p1[an][1]);
        }
        __syncwarp();
        __syncthreads();   // Vs fully written by all threads

        // O += P @ V   (m16 x n64 x k64 per warp)
#pragma unroll
        for (int kk = 0; kk < 64; kk += 8) {
            uint32_t a0 = Pw[lq * 68 + kk + lr];
            uint32_t a1 = Pw[(lq + 8) * 68 + kk + lr];
            uint32_t a2 = Pw[lq * 68 + kk + 4 + lr];
            uint32_t a3 = Pw[(lq + 8) * 68 + kk + 4 + lr];
#pragma unroll
            for (int an = 0; an < 8; an++) {
                uint32_t b0 = Vs[kk + lr][an * 8 + lq];
                uint32_t b1 = Vs[kk + 4 + lr][an * 8 + lq];
                mma_tf32(acc[an], a0, a1, a2, a3, b0, b1);
            }
        }
    }

    // epilogue: normalize and write ctx
    float inv0 = 1.f / l0, inv1 = 1.f / l1;
#pragma unroll
    for (int an = 0; an < 8; an++) {
        int col = an * 8 + 2 * lr;
        float2 v0 = make_float2(acc[an][0] * inv0, acc[an][1] * inv0);
        float2 v1 = make_float2(acc[an][2] * inv1, acc[an][3] * inv1);
        *(float2*)&Ctx[(size_t)(b * SS + r0) * DD + h * DHH + col] = v0;
        *(float2*)&Ctx[(size_t)(b * SS + r1) * DD + h * DHH + col] = v1;
    }
}

// ---------------- launcher ------------------------------------------------------
extern "C" void kernel_launch(void* const* d_in, const int* in_sizes, int n_in,
                              void* d_out, int out_size)
{
    (void)in_sizes; (void)n_in; (void)out_size;
    const float* query = (const float*)d_in[0];
    const float* key   = (const float*)d_in[1];
    const float* value = (const float*)d_in[2];
    const float* pose  = (const float*)d_in[3];
    const float* Wq = (const float*)d_in[4];
    const float* bq = (const float*)d_in[5];
    const float* Wk = (const float*)d_in[6];
    const float* bk = (const float*)d_in[7];
    const float* Wv = (const float*)d_in[8];
    const float* bv = (const float*)d_in[9];
    const float* Wp = (const float*)d_in[10];
    const float* ub = (const float*)d_in[11];
    const float* vb = (const float*)d_in[12];
    const float* Wo = (const float*)d_in[13];
    const float* bo = (const float*)d_in[14];
    float* out = (float*)d_out;

    float *qu, *qv, *kk, *vv, *pp, *C, *M, *ctx;
    cudaGetSymbolAddress((void**)&qu,  g_qu);
    cudaGetSymbolAddress((void**)&qv,  g_qv);
    cudaGetSymbolAddress((void**)&kk,  g_k);
    cudaGetSymbolAddress((void**)&vv,  g_v);
    cudaGetSymbolAddress((void**)&pp,  g_p);
    cudaGetSymbolAddress((void**)&C,   g_C);
    cudaGetSymbolAddress((void**)&M,   g_M);
    cudaGetSymbolAddress((void**)&ctx, g_ctx);

    cudaFuncSetAttribute(fa_kernel, cudaFuncAttributeMaxDynamicSharedMemorySize,
                         FA_SMEM_BYTES);

    dim3 pg(DD / 128, MTOT / 128);         // (4, 64)
    proj_kernel<<<pg, 256>>>(query, Wq, bq, qu, ub, qv, vb);
    proj_kernel<<<pg, 256>>>(key,   Wk, bk, kk, nullptr, nullptr, nullptr);
    proj_kernel<<<pg, 256>>>(value, Wv, bv, vv, nullptr, nullptr, nullptr);
    proj_kernel<<<pg, 256>>>(pose,  Wp, nullptr, pp, nullptr, nullptr, nullptr);

    dim3 sg(SS / 64, SS / 64, BH);         // (16,16,64)
    score_kernel<<<sg, 256>>>(qu, kk, C);
    score_kernel<<<sg, 256>>>(qv, pp, M);

    dim3 fg(SS / 128, BH);                 // (8, 64)
    fa_kernel<<<fg, 256, FA_SMEM_BYTES>>>(C, M, vv, ctx);

    proj_kernel<<<pg, 256>>>(ctx, Wo, bo, out, nullptr, nullptr, nullptr);
}

// round 4
// speedup vs baseline: 2.1157x; 1.2874x over previous
#include <cuda_runtime.h>
#include <cstdint>

#define BB 8
#define SS 1024
#define DD 512
#define HH 8
#define DHH 64
#define MTOT (BB*SS)   // 8192
#define BH   (BB*HH)   // 64

// ---------------- scratch (__device__ globals) ---------------------------------
__device__ float g_qu[MTOT*DD];                 // q + u_bias
__device__ float g_qv[MTOT*DD];                 // q + v_bias
__device__ float g_k [MTOT*DD];
__device__ float g_v [MTOT*DD];
__device__ float g_p [MTOT*DD];
__device__ float g_M [BH*SS*SS];                // pos scores pre-shift (256 MB)
__device__ float g_ctx[MTOT*DD];

// ---------------- tf32 helpers -------------------------------------------------
__device__ __forceinline__ uint32_t f2tf(float x) {
    uint32_t r;
    asm("cvt.rna.tf32.f32 %0, %1;" : "=r"(r) : "f"(x));
    return r;
}

__device__ __forceinline__ void mma_tf32(float c[4],
                                         uint32_t a0, uint32_t a1, uint32_t a2, uint32_t a3,
                                         uint32_t b0, uint32_t b1)
{
    asm volatile(
        "mma.sync.aligned.m16n8k8.row.col.f32.tf32.tf32.f32 "
        "{%0,%1,%2,%3}, {%4,%5,%6,%7}, {%8,%9}, {%0,%1,%2,%3};"
        : "+f"(c[0]), "+f"(c[1]), "+f"(c[2]), "+f"(c[3])
        : "r"(a0), "r"(a1), "r"(a2), "r"(a3), "r"(b0), "r"(b1));
}

// ---------------- kernel 1: projection GEMM ------------------------------------
// C[8192,512] = A[8192,512] @ W[512,512]. Block 128x128, K-step 16, reg prefetch.
// Odd smem stride (133) -> <=2-way conflicts on transposed stores + frag loads.
__global__ void __launch_bounds__(256, 2)
proj_kernel(const float* __restrict__ A, const float* __restrict__ W,
            const float* __restrict__ bias,
            float* __restrict__ out0, const float* __restrict__ ex0,
            float* __restrict__ out1, const float* __restrict__ ex1)
{
    __shared__ uint32_t As[16][133];   // As[k][m]
    __shared__ uint32_t Bs[16][133];   // Bs[k][n]
    const int tid  = threadIdx.x;
    const int lane = tid & 31, w = tid >> 5;
    const int wm = w & 1, wn = w >> 1;            // 2 x 4
    const int m_w = wm * 64, n_w = wn * 32;
    const int m0 = blockIdx.y * 128, n0 = blockIdx.x * 128;
    const int lq = lane >> 2, lr = lane & 3;

    const int a_row = tid >> 2;                    // 0..63 (t adds 64)
    const int a_c4  = (tid & 3) * 4;
    const int b_row = tid >> 5;                    // 0..7  (t adds 8)
    const int b_c4  = (tid & 31) * 4;

    float4 pa[2], pb[2];
#pragma unroll
    for (int t = 0; t < 2; t++)
        pa[t] = *(const float4*)&A[(m0 + a_row + t * 64) * DD + a_c4];
#pragma unroll
    for (int t = 0; t < 2; t++)
        pb[t] = *(const float4*)&W[(b_row + t * 8) * DD + n0 + b_c4];

    float acc[4][4][4] = {};

    for (int k0 = 0; k0 < DD; k0 += 16) {
#pragma unroll
        for (int t = 0; t < 2; t++) {
            int row = a_row + t * 64;
            As[a_c4 + 0][row] = f2tf(pa[t].x); As[a_c4 + 1][row] = f2tf(pa[t].y);
            As[a_c4 + 2][row] = f2tf(pa[t].z); As[a_c4 + 3][row] = f2tf(pa[t].w);
        }
#pragma unroll
        for (int t = 0; t < 2; t++) {
            int row = b_row + t * 8;
            Bs[row][b_c4 + 0] = f2tf(pb[t].x); Bs[row][b_c4 + 1] = f2tf(pb[t].y);
            Bs[row][b_c4 + 2] = f2tf(pb[t].z); Bs[row][b_c4 + 3] = f2tf(pb[t].w);
        }
        __syncthreads();
        if (k0 + 16 < DD) {
#pragma unroll
            for (int t = 0; t < 2; t++)
                pa[t] = *(const float4*)&A[(m0 + a_row + t * 64) * DD + k0 + 16 + a_c4];
#pragma unroll
            for (int t = 0; t < 2; t++)
                pb[t] = *(const float4*)&W[(k0 + 16 + b_row + t * 8) * DD + n0 + b_c4];
        }
#pragma unroll
        for (int kk = 0; kk < 16; kk += 8) {
            uint32_t a[4][4], b[4][2];
#pragma unroll
            for (int am = 0; am < 4; am++) {
                int mb = m_w + am * 16;
                a[am][0] = As[kk + lr][mb + lq];
                a[am][1] = As[kk + lr][mb + 8 + lq];
                a[am][2] = As[kk + 4 + lr][mb + lq];
                a[am][3] = As[kk + 4 + lr][mb + 8 + lq];
            }
#pragma unroll
            for (int an = 0; an < 4; an++) {
                int nb = n_w + an * 8;
                b[an][0] = Bs[kk + lr][nb + lq];
                b[an][1] = Bs[kk + 4 + lr][nb + lq];
            }
#pragma unroll
            for (int am = 0; am < 4; am++)
#pragma unroll
                for (int an = 0; an < 4; an++)
                    mma_tf32(acc[am][an], a[am][0], a[am][1], a[am][2], a[am][3],
                             b[an][0], b[an][1]);
        }
        __syncthreads();
    }

#pragma unroll
    for (int am = 0; am < 4; am++) {
#pragma unroll
        for (int an = 0; an < 4; an++) {
#pragma unroll
            for (int half = 0; half < 2; half++) {
                int row = m0 + m_w + am * 16 + lq + half * 8;
                int col = n0 + n_w + an * 8 + lr * 2;
                float v0 = acc[am][an][half * 2 + 0];
                float v1 = acc[am][an][half * 2 + 1];
                if (bias) { v0 += bias[col]; v1 += bias[col + 1]; }
                if (out0) {
                    float e0 = ex0 ? ex0[col] : 0.f, e1 = ex0 ? ex0[col + 1] : 0.f;
                    float2 vv = make_float2(v0 + e0, v1 + e1);
                    *(float2*)&out0[(size_t)row * DD + col] = vv;
                }
                if (out1) {
                    float e0 = ex1 ? ex1[col] : 0.f, e1 = ex1 ? ex1[col + 1] : 0.f;
                    float2 vv = make_float2(v0 + e0, v1 + e1);
                    *(float2*)&out1[(size_t)row * DD + col] = vv;
                }
            }
        }
    }
}

// ---------------- kernel 2: pos-score GEMM (M) ---------------------------------
// M[z,i,j] = sum_d QV[b,i,h*64+d] * P[b,j,h*64+d]. Block 128x128, single K=64 pass.
#define SC_SMEM_BYTES (2 * 64 * 133 * 4)
__global__ void __launch_bounds__(256, 2)
score_kernel(const float* __restrict__ Qm, const float* __restrict__ Km,
             float* __restrict__ Out)
{
    extern __shared__ uint32_t sm2[];
    uint32_t (*As)[133] = (uint32_t(*)[133])sm2;            // [d][i]
    uint32_t (*Bs)[133] = (uint32_t(*)[133])(sm2 + 64*133); // [d][j]
    const int tid  = threadIdx.x;
    const int lane = tid & 31, w = tid >> 5;
    const int wm = w & 1, wn = w >> 1;
    const int m_w = wm * 64, n_w = wn * 32;
    const int z = blockIdx.z, b = z >> 3, h = z & 7;
    const int i0 = blockIdx.y * 128, j0 = blockIdx.x * 128;
    const int lq = lane >> 2, lr = lane & 3;
    const float* Qb = Qm + (size_t)(b * SS) * DD + h * DHH;
    const float* Kb = Km + (size_t)(b * SS) * DD + h * DHH;

#pragma unroll
    for (int t = 0; t < 8; t++) {
        int id = tid + t * 256;            // 0..2047
        int row = id >> 4;                 // 0..127
        int c4  = (id & 15) * 4;           // 0..60
        float4 q4 = *(const float4*)&Qb[(size_t)(i0 + row) * DD + c4];
        As[c4 + 0][row] = f2tf(q4.x); As[c4 + 1][row] = f2tf(q4.y);
        As[c4 + 2][row] = f2tf(q4.z); As[c4 + 3][row] = f2tf(q4.w);
        float4 k4 = *(const float4*)&Kb[(size_t)(j0 + row) * DD + c4];
        Bs[c4 + 0][row] = f2tf(k4.x); Bs[c4 + 1][row] = f2tf(k4.y);
        Bs[c4 + 2][row] = f2tf(k4.z); Bs[c4 + 3][row] = f2tf(k4.w);
    }
    __syncthreads();

    float acc[4][4][4] = {};
#pragma unroll
    for (int kk = 0; kk < 64; kk += 8) {
        uint32_t a[4][4], b2[4][2];
#pragma unroll
        for (int am = 0; am < 4; am++) {
            int mb = m_w + am * 16;
            a[am][0] = As[kk + lr][mb + lq];
            a[am][1] = As[kk + lr][mb + 8 + lq];
            a[am][2] = As[kk + 4 + lr][mb + lq];
            a[am][3] = As[kk + 4 + lr][mb + 8 + lq];
        }
#pragma unroll
        for (int an = 0; an < 4; an++) {
            int nb = n_w + an * 8;
            b2[an][0] = Bs[kk + lr][nb + lq];
            b2[an][1] = Bs[kk + 4 + lr][nb + lq];
        }
#pragma unroll
        for (int am = 0; am < 4; am++)
#pragma unroll
            for (int an = 0; an < 4; an++)
                mma_tf32(acc[am][an], a[am][0], a[am][1], a[am][2], a[am][3],
                         b2[an][0], b2[an][1]);
    }

#pragma unroll
    for (int am = 0; am < 4; am++) {
#pragma unroll
        for (int an = 0; an < 4; an++) {
#pragma unroll
            for (int half = 0; half < 2; half++) {
                int row = i0 + m_w + am * 16 + lq + half * 8;
                int col = j0 + n_w + an * 8 + lr * 2;
                float2 vv = make_float2(acc[am][an][half * 2 + 0],
                                        acc[am][an][half * 2 + 1]);
                *(float2*)&Out[((size_t)z * SS + row) * SS + col] = vv;
            }
        }
    }
}

// ---------------- kernel 3: fused QK^T + shift + softmax + PV ------------------
// grid (S/128, BH), 256 thr = 8 warps; warp w owns rows [i0+16w, i0+16w+16).
// Q tile resident; per j-tile: K tile -> S via MMA, M band gather, online
// softmax, P -> per-warp smem -> PV MMA vs V tile.
#define FA_SMEM_BYTES ((64*133 + 64*69 + 64*69 + 8*16*68) * 4)
__global__ void __launch_bounds__(256, 2)
fa_kernel(const float* __restrict__ Qu, const float* __restrict__ Km,
          const float* __restrict__ M, const float* __restrict__ V,
          float* __restrict__ Ctx)
{
    extern __shared__ uint32_t sm[];
    uint32_t (*Qs)[133] = (uint32_t(*)[133])sm;                       // [d][i]
    uint32_t (*Ks)[69]  = (uint32_t(*)[69])(sm + 64*133);             // [d][j]
    uint32_t (*Vs)[69]  = (uint32_t(*)[69])(sm + 64*133 + 64*69);     // [j][d]
    uint32_t* Ps        = sm + 64*133 + 2*64*69;                      // 8 x [16][68]

    const int tid  = threadIdx.x;
    const int lane = tid & 31, w = tid >> 5;
    const int lq = lane >> 2, lr = lane & 3;
    const int z = blockIdx.y, b = z >> 3, h = z & 7;
    const int i0 = blockIdx.x * 128;
    const int m_w = w * 16;
    const int r0 = i0 + m_w + lq;
    const int r1 = r0 + 8;

    const float* Qb = Qu + ((size_t)(b * SS) + i0) * DD + h * DHH;
    const float* Kb = Km + (size_t)(b * SS) * DD + h * DHH;
    const float* Vb = V  + (size_t)(b * SS) * DD + h * DHH;
    const float* Mrow0 = M + ((size_t)z * SS + r0) * SS;
    const float* Mrow1 = M + ((size_t)z * SS + r1) * SS;
    uint32_t* Pw = Ps + w * (16 * 68);

    const float scale = 0.04419417382415922f;   // 1/sqrt(512)

    // resident Q tile [128 x 64] -> Qs[d][i]
#pragma unroll
    for (int t = 0; t < 8; t++) {
        int id = tid + t * 256;
        int row = id >> 4;
        int c4  = (id & 15) * 4;
        float4 q4 = *(const float4*)&Qb[(size_t)row * DD + c4];
        Qs[c4 + 0][row] = f2tf(q4.x); Qs[c4 + 1][row] = f2tf(q4.y);
        Qs[c4 + 2][row] = f2tf(q4.z); Qs[c4 + 3][row] = f2tf(q4.w);
    }

    float acc[8][4] = {};
    float rm0 = -1e30f, rm1 = -1e30f, l0 = 0.f, l1 = 0.f;

    for (int j0 = 0; j0 < SS; j0 += 64) {
        __syncthreads();   // WAR on Ks/Vs from previous iteration's MMAs
#pragma unroll
        for (int t = 0; t < 4; t++) {
            int id = tid + t * 256;
            int row = id >> 4;
            int c4  = (id & 15) * 4;
            float4 k4 = *(const float4*)&Kb[(size_t)(j0 + row) * DD + c4];
            Ks[c4 + 0][row] = f2tf(k4.x); Ks[c4 + 1][row] = f2tf(k4.y);
            Ks[c4 + 2][row] = f2tf(k4.z); Ks[c4 + 3][row] = f2tf(k4.w);
            float4 v4 = *(const float4*)&Vb[(size_t)(j0 + row) * DD + c4];
            Vs[row][c4 + 0] = f2tf(v4.x); Vs[row][c4 + 1] = f2tf(v4.y);
            Vs[row][c4 + 2] = f2tf(v4.z); Vs[row][c4 + 3] = f2tf(v4.w);
        }
        __syncthreads();

        // S = Q K^T  (warp: 16 rows x 64 j)
        float s[8][4] = {};
#pragma unroll
        for (int kk = 0; kk < 64; kk += 8) {
            uint32_t a0 = Qs[kk + lr][m_w + lq];
            uint32_t a1 = Qs[kk + lr][m_w + 8 + lq];
            uint32_t a2 = Qs[kk + 4 + lr][m_w + lq];
            uint32_t a3 = Qs[kk + 4 + lr][m_w + 8 + lq];
#pragma unroll
            for (int an = 0; an < 8; an++) {
                uint32_t b0 = Ks[kk + lr][an * 8 + lq];
                uint32_t b1 = Ks[kk + 4 + lr][an * 8 + lq];
                mma_tf32(s[an], a0, a1, a2, a3, b0, b1);
            }
        }

        // add rel-shifted pos scores, scale, track tile max
        float tm0 = -1e30f, tm1 = -1e30f;
#pragma unroll
        for (int an = 0; an < 8; an++) {
#pragma unroll
            for (int e = 0; e < 2; e++) {
                int j = j0 + an * 8 + 2 * lr + e;
                float pv0, pv1;
                if (j <= r0)          pv0 = Mrow0[SS - 1 - r0 + j];
                else if (j == r0 + 1) pv0 = 0.f;
                else                  pv0 = Mrow0[SS + (j - r0 - 2)];
                if (j <= r1)          pv1 = Mrow1[SS - 1 - r1 + j];
                else if (j == r1 + 1) pv1 = 0.f;
                else                  pv1 = Mrow1[SS + (j - r1 - 2)];
                float s0 = (s[an][e]     + pv0) * scale;
                float s1 = (s[an][2 + e] + pv1) * scale;
                s[an][e] = s0; s[an][2 + e] = s1;
                tm0 = fmaxf(tm0, s0); tm1 = fmaxf(tm1, s1);
            }
        }
        tm0 = fmaxf(tm0, __shfl_xor_sync(0xffffffffu, tm0, 1));
        tm0 = fmaxf(tm0, __shfl_xor_sync(0xffffffffu, tm0, 2));
        tm1 = fmaxf(tm1, __shfl_xor_sync(0xffffffffu, tm1, 1));
        tm1 = fmaxf(tm1, __shfl_xor_sync(0xffffffffu, tm1, 2));

        float nm0 = fmaxf(rm0, tm0), nm1 = fmaxf(rm1, tm1);
        float al0 = __expf(rm0 - nm0), al1 = __expf(rm1 - nm1);
        float sum0 = 0.f, sum1 = 0.f;
#pragma unroll
        for (int an = 0; an < 8; an++)
#pragma unroll
            for (int e = 0; e < 2; e++) {
                s[an][e]     = __expf(s[an][e]     - nm0); sum0 += s[an][e];
                s[an][2 + e] = __expf(s[an][2 + e] - nm1); sum1 += s[an][2 + e];
            }
        sum0 += __shfl_xor_sync(0xffffffffu, sum0, 1);
        sum0 += __shfl_xor_sync(0xffffffffu, sum0, 2);
        sum1 += __shfl_xor_sync(0xffffffffu, sum1, 1);
        sum1 += __shfl_xor_sync(0xffffffffu, sum1, 2);
        l0 = l0 * al0 + sum0; l1 = l1 * al1 + sum1;
        rm0 = nm0; rm1 = nm1;

#pragma unroll
        for (int an = 0; an < 8; an++) {
            acc[an][0] *= al0; acc[an][1] *= al0;
            acc[an][2] *= al1; acc[an][3] *= al1;
        }
        // P -> per-warp smem (tf32)
#pragma unroll
        for (int an = 0; an < 8; an++) {
            int col = an * 8 + 2 * lr;
            Pw[lq * 68 + col]           = f2tf(s[an][0]);
            Pw[lq * 68 + col + 1]       = f2tf(s[an][1]);
            Pw[(lq + 8) * 68 + col]     = f2tf(s[an][2]);
            Pw[(lq + 8) * 68 + col + 1] = f2tf(s[an][3]);
        }
        __syncwarp();

        // O += P @ V
#pragma unroll
        for (int kk = 0; kk < 64; kk += 8) {
            uint32_t a0 = Pw[lq * 68 + kk + lr];
            uint32_t a1 = Pw[(lq + 8) * 68 + kk + lr];
            uint32_t a2 = Pw[lq * 68 + kk + 4 + lr];
            uint32_t a3 = Pw[(lq + 8) * 68 + kk + 4 + lr];
#pragma unroll
            for (int an = 0; an < 8; an++) {
                uint32_t b0 = Vs[kk + lr][an * 8 + lq];
                uint32_t b1 = Vs[kk + 4 + lr][an * 8 + lq];
                mma_tf32(acc[an], a0, a1, a2, a3, b0, b1);
            }
        }
    }

    float inv0 = 1.f / l0, inv1 = 1.f / l1;
#pragma unroll
    for (int an = 0; an < 8; an++) {
        int col = an * 8 + 2 * lr;
        float2 v0 = make_float2(acc[an][0] * inv0, acc[an][1] * inv0);
        float2 v1 = make_float2(acc[an][2] * inv1, acc[an][3] * inv1);
        *(float2*)&Ctx[(size_t)(b * SS + r0) * DD + h * DHH + col] = v0;
        *(float2*)&Ctx[(size_t)(b * SS + r1) * DD + h * DHH + col] = v1;
    }
}

// ---------------- launcher ------------------------------------------------------
extern "C" void kernel_launch(void* const* d_in, const int* in_sizes, int n_in,
                              void* d_out, int out_size)
{
    (void)in_sizes; (void)n_in; (void)out_size;
    const float* query = (const float*)d_in[0];
    const float* key   = (const float*)d_in[1];
    const float* value = (const float*)d_in[2];
    const float* pose  = (const float*)d_in[3];
    const float* Wq = (const float*)d_in[4];
    const float* bq = (const float*)d_in[5];
    const float* Wk = (const float*)d_in[6];
    const float* bk = (const float*)d_in[7];
    const float* Wv = (const float*)d_in[8];
    const float* bv = (const float*)d_in[9];
    const float* Wp = (const float*)d_in[10];
    const float* ub = (const float*)d_in[11];
    const float* vb = (const float*)d_in[12];
    const float* Wo = (const float*)d_in[13];
    const float* bo = (const float*)d_in[14];
    float* out = (float*)d_out;

    float *qu, *qv, *kk, *vv, *pp, *M, *ctx;
    cudaGetSymbolAddress((void**)&qu,  g_qu);
    cudaGetSymbolAddress((void**)&qv,  g_qv);
    cudaGetSymbolAddress((void**)&kk,  g_k);
    cudaGetSymbolAddress((void**)&vv,  g_v);
    cudaGetSymbolAddress((void**)&pp,  g_p);
    cudaGetSymbolAddress((void**)&M,   g_M);
    cudaGetSymbolAddress((void**)&ctx, g_ctx);

    cudaFuncSetAttribute(score_kernel, cudaFuncAttributeMaxDynamicSharedMemorySize,
                         SC_SMEM_BYTES);
    cudaFuncSetAttribute(fa_kernel, cudaFuncAttributeMaxDynamicSharedMemorySize,
                         FA_SMEM_BYTES);

    dim3 pg(DD / 128, MTOT / 128);         // (4, 64)
    proj_kernel<<<pg, 256>>>(query, Wq, bq, qu, ub, qv, vb);
    proj_kernel<<<pg, 256>>>(key,   Wk, bk, kk, nullptr, nullptr, nullptr);
    proj_kernel<<<pg, 256>>>(value, Wv, bv, vv, nullptr, nullptr, nullptr);
    proj_kernel<<<pg, 256>>>(pose,  Wp, nullptr, pp, nullptr, nullptr, nullptr);

    dim3 sg(SS / 128, SS / 128, BH);       // (8,8,64)
    score_kernel<<<sg, 256, SC_SMEM_BYTES>>>(qv, pp, M);

    dim3 fg(SS / 128, BH);                 // (8, 64)
    fa_kernel<<<fg, 256, FA_SMEM_BYTES>>>(qu, kk, M, vv, ctx);

    proj_kernel<<<pg, 256>>>(ctx, Wo, bo, out, nullptr, nullptr, nullptr);
}

// round 5
// speedup vs baseline: 2.2110x; 1.0450x over previous
#include <cuda_runtime.h>
#include <cstdint>

#define BB 8
#define SS 1024
#define DD 512
#define HH 8
#define DHH 64
#define MTOT (BB*SS)   // 8192
#define BH   (BB*HH)   // 64

// ---------------- scratch (__device__ globals) ---------------------------------
__device__ float g_qu[MTOT*DD];                 // q + u_bias
__device__ float g_qv[MTOT*DD];                 // q + v_bias
__device__ float g_k [MTOT*DD];
__device__ float g_v [MTOT*DD];
__device__ float g_p [MTOT*DD];
__device__ float g_M [BH*SS*SS];                // pos scores pre-shift (256 MB)
__device__ float g_ctx[MTOT*DD];

// ---------------- tf32 helpers -------------------------------------------------
__device__ __forceinline__ uint32_t f2tf(float x) {
    uint32_t r;
    asm("cvt.rna.tf32.f32 %0, %1;" : "=r"(r) : "f"(x));
    return r;
}

__device__ __forceinline__ void mma_tf32(float c[4],
                                         uint32_t a0, uint32_t a1, uint32_t a2, uint32_t a3,
                                         uint32_t b0, uint32_t b1)
{
    asm volatile(
        "mma.sync.aligned.m16n8k8.row.col.f32.tf32.tf32.f32 "
        "{%0,%1,%2,%3}, {%4,%5,%6,%7}, {%8,%9}, {%0,%1,%2,%3};"
        : "+f"(c[0]), "+f"(c[1]), "+f"(c[2]), "+f"(c[3])
        : "r"(a0), "r"(a1), "r"(a2), "r"(a3), "r"(b0), "r"(b1));
}

// ---------------- fragment-major smem layouts ----------------------------------
// A-frag (m16 x k8 atoms): block = ma*KB + kb, block stride 132 words.
//   word = block*132 + lane*4 + reg;  lane = 4*(m&7)+(k&3);
//   reg  = ((m>>3)&1) + 2*((k>>2)&1)   (matches mma a0..a3 order)
__device__ __forceinline__ void ldA(uint32_t a[4], const uint32_t* buf, int KB,
                                    int ma, int kb, int lane)
{
    const uint32_t* p = buf + (ma * KB + kb) * 132 + lane * 4;
    uint4 v = *(const uint4*)p;
    a[0] = v.x; a[1] = v.y; a[2] = v.z; a[3] = v.w;
}
// store float4 of 4 consecutive k (k%4==0) at row m
__device__ __forceinline__ void stA(uint32_t* buf, int KB, int m, int k, float4 v)
{
    uint32_t e[4] = {f2tf(v.x), f2tf(v.y), f2tf(v.z), f2tf(v.w)};
    uint32_t* p = buf + ((m >> 4) * KB + (k >> 3)) * 132
                + ((m >> 3) & 1) + 2 * ((k >> 2) & 1);
    int lb = 4 * (m & 7);
    int rot = ((m >> 1) + (k >> 2)) & 3;
#pragma unroll
    for (int i = 0; i < 4; i++) {
        int j = (i + rot) & 3;
        p[(lb + j) * 4] = e[j];
    }
}

// B-frag (n8 x k8 atoms): block = na*KB + kb, block stride 66 words.
//   word = block*66 + lane*2 + reg;  lane = 4*(n&7)+(k&3);  reg = (k>>2)&1
__device__ __forceinline__ void ldB(uint32_t b[2], const uint32_t* buf, int KB,
                                    int na, int kb, int lane)
{
    const uint32_t* p = buf + (na * KB + kb) * 66 + lane * 2;
    uint2 v = *(const uint2*)p;
    b[0] = v.x; b[1] = v.y;
}
// store float4 of 4 consecutive n (n%4==0) at row k  (source row-major [k][n])
__device__ __forceinline__ void stB_nquad(uint32_t* buf, int KB, int k, int n, float4 v)
{
    uint32_t e[4] = {f2tf(v.x), f2tf(v.y), f2tf(v.z), f2tf(v.w)};
    int kb = k >> 3, reg = (k >> 2) & 1;
    int rot = ((n >> 2) + k) & 3;
#pragma unroll
    for (int i = 0; i < 4; i++) {
        int j = (i + rot) & 3;
        int nn = n + j;
        buf[((nn >> 3) * KB + kb) * 66 + (4 * (nn & 7) + (k & 3)) * 2 + reg] = e[j];
    }
}
// store float4 of 4 consecutive k (k%4==0) at row n  (source row-major [n][k])
__device__ __forceinline__ void stB_kquad(uint32_t* buf, int KB, int n, int k, float4 v)
{
    uint32_t e[4] = {f2tf(v.x), f2tf(v.y), f2tf(v.z), f2tf(v.w)};
    int lb = 4 * (n & 7);
    uint32_t* p = buf + ((n >> 3) * KB + (k >> 3)) * 66 + ((k >> 2) & 1);
    int rot = ((n >> 1) + (k >> 2)) & 3;
#pragma unroll
    for (int i = 0; i < 4; i++) {
        int j = (i + rot) & 3;
        p[(lb + ((k + j) & 3)) * 2] = e[j];
    }
}

// ---------------- kernel 1: projection GEMM (merged, frag-major) ---------------
struct ProjSet {
    const float *A, *W, *bias, *ex0, *ex1;
    float *out0, *out1;
};
struct ProjArgs { ProjSet s[4]; };

__global__ void __launch_bounds__(256, 2)
proj_kernel(ProjArgs args)
{
    __shared__ uint32_t Af[16 * 132];   // 8 ma x 2 kb
    __shared__ uint32_t Bf[32 * 66];    // 16 na x 2 kb
    const ProjSet ps = args.s[blockIdx.z];
    const float* __restrict__ A = ps.A;
    const float* __restrict__ W = ps.W;

    const int tid  = threadIdx.x;
    const int lane = tid & 31, w = tid >> 5;
    const int wm = w & 1, wn = w >> 1;            // 2 x 4 warps, warp tile 64x32
    const int m_w = wm * 64, n_w = wn * 32;
    const int m0 = blockIdx.y * 128, n0 = blockIdx.x * 128;
    const int lq = lane >> 2, lr = lane & 3;

    const int a_row = tid >> 2;                    // 0..63 (t adds 64)
    const int a_c4  = (tid & 3) * 4;               // k: 0,4,8,12
    const int b_k   = tid & 15;                    // k: 0..15
    const int b_n4  = (tid >> 4) * 4;              // n: 0..60 (t adds 64)

    float4 pa[2], pb[2];
#pragma unroll
    for (int t = 0; t < 2; t++)
        pa[t] = *(const float4*)&A[(size_t)(m0 + a_row + t * 64) * DD + a_c4];
#pragma unroll
    for (int t = 0; t < 2; t++)
        pb[t] = *(const float4*)&W[(size_t)b_k * DD + n0 + b_n4 + t * 64];

    float acc[4][4][4] = {};

    for (int k0 = 0; k0 < DD; k0 += 16) {
#pragma unroll
        for (int t = 0; t < 2; t++)
            stA(Af, 2, a_row + t * 64, a_c4, pa[t]);
#pragma unroll
        for (int t = 0; t < 2; t++)
            stB_nquad(Bf, 2, b_k, b_n4 + t * 64, pb[t]);
        __syncthreads();
        if (k0 + 16 < DD) {
#pragma unroll
            for (int t = 0; t < 2; t++)
                pa[t] = *(const float4*)&A[(size_t)(m0 + a_row + t * 64) * DD + k0 + 16 + a_c4];
#pragma unroll
            for (int t = 0; t < 2; t++)
                pb[t] = *(const float4*)&W[(size_t)(k0 + 16 + b_k) * DD + n0 + b_n4 + t * 64];
        }
#pragma unroll
        for (int kb = 0; kb < 2; kb++) {
            uint32_t a[4][4], b[4][2];
#pragma unroll
            for (int am = 0; am < 4; am++)
                ldA(a[am], Af, 2, wm * 4 + am, kb, lane);
#pragma unroll
            for (int an = 0; an < 4; an++)
                ldB(b[an], Bf, 2, wn * 4 + an, kb, lane);
#pragma unroll
            for (int am = 0; am < 4; am++)
#pragma unroll
                for (int an = 0; an < 4; an++)
                    mma_tf32(acc[am][an], a[am][0], a[am][1], a[am][2], a[am][3],
                             b[an][0], b[an][1]);
        }
        __syncthreads();
    }

#pragma unroll
    for (int am = 0; am < 4; am++) {
#pragma unroll
        for (int an = 0; an < 4; an++) {
#pragma unroll
            for (int half = 0; half < 2; half++) {
                int row = m0 + m_w + am * 16 + lq + half * 8;
                int col = n0 + n_w + an * 8 + lr * 2;
                float v0 = acc[am][an][half * 2 + 0];
                float v1 = acc[am][an][half * 2 + 1];
                if (ps.bias) { v0 += ps.bias[col]; v1 += ps.bias[col + 1]; }
                if (ps.out0) {
                    float e0 = ps.ex0 ? ps.ex0[col] : 0.f;
                    float e1 = ps.ex0 ? ps.ex0[col + 1] : 0.f;
                    float2 vv = make_float2(v0 + e0, v1 + e1);
                    *(float2*)&ps.out0[(size_t)row * DD + col] = vv;
                }
                if (ps.out1) {
                    float e0 = ps.ex1 ? ps.ex1[col] : 0.f;
                    float e1 = ps.ex1 ? ps.ex1[col + 1] : 0.f;
                    float2 vv = make_float2(v0 + e0, v1 + e1);
                    *(float2*)&ps.out1[(size_t)row * DD + col] = vv;
                }
            }
        }
    }
}

// ---------------- kernel 2: pos-score GEMM (M), frag-major ---------------------
#define SC_SMEM_BYTES ((64*132 + 128*66) * 4)
__global__ void __launch_bounds__(256, 2)
score_kernel(const float* __restrict__ Qm, const float* __restrict__ Km,
             float* __restrict__ Out)
{
    extern __shared__ uint32_t sm2[];
    uint32_t* Qf = sm2;              // 8 ma x 8 kb
    uint32_t* Kf = sm2 + 64 * 132;   // 16 na x 8 kb
    const int tid  = threadIdx.x;
    const int lane = tid & 31, w = tid >> 5;
    const int wm = w & 1, wn = w >> 1;
    const int m_w = wm * 64, n_w = wn * 32;
    const int z = blockIdx.z, b = z >> 3, h = z & 7;
    const int i0 = blockIdx.y * 128, j0 = blockIdx.x * 128;
    const int lq = lane >> 2, lr = lane & 3;
    const float* Qb = Qm + (size_t)(b * SS) * DD + h * DHH;
    const float* Kb = Km + (size_t)(b * SS) * DD + h * DHH;

#pragma unroll
    for (int t = 0; t < 8; t++) {
        int id = tid + t * 256;            // 0..2047
        int row = id >> 4;                 // 0..127
        int c4  = (id & 15) * 4;           // 0..60
        float4 q4 = *(const float4*)&Qb[(size_t)(i0 + row) * DD + c4];
        stA(Qf, 8, row, c4, q4);
        float4 k4 = *(const float4*)&Kb[(size_t)(j0 + row) * DD + c4];
        stB_kquad(Kf, 8, row, c4, k4);
    }
    __syncthreads();

    float acc[4][4][4] = {};
#pragma unroll
    for (int kb = 0; kb < 8; kb++) {
        uint32_t a[4][4], b2[4][2];
#pragma unroll
        for (int am = 0; am < 4; am++)
            ldA(a[am], Qf, 8, wm * 4 + am, kb, lane);
#pragma unroll
        for (int an = 0; an < 4; an++)
            ldB(b2[an], Kf, 8, wn * 4 + an, kb, lane);
#pragma unroll
        for (int am = 0; am < 4; am++)
#pragma unroll
            for (int an = 0; an < 4; an++)
                mma_tf32(acc[am][an], a[am][0], a[am][1], a[am][2], a[am][3],
                         b2[an][0], b2[an][1]);
    }

#pragma unroll
    for (int am = 0; am < 4; am++) {
#pragma unroll
        for (int an = 0; an < 4; an++) {
#pragma unroll
            for (int half = 0; half < 2; half++) {
                int row = i0 + m_w + am * 16 + lq + half * 8;
                int col = j0 + n_w + an * 8 + lr * 2;
                float2 vv = make_float2(acc[am][an][half * 2 + 0],
                                        acc[am][an][half * 2 + 1]);
                *(float2*)&Out[((size_t)z * SS + row) * SS + col] = vv;
            }
        }
    }
}

// ---------------- kernel 3: fused QK^T + shift + softmax + PV ------------------
// Qf 64 blk x132, Kf 64 blk x66, Vf 64 blk x66, Pf 8 warps x (8 blk x132)
#define FA_SMEM_BYTES ((64*132 + 64*66 + 64*66 + 8*8*132) * 4)
__global__ void __launch_bounds__(256, 2)
fa_kernel(const float* __restrict__ Qu, const float* __restrict__ Km,
          const float* __restrict__ M, const float* __restrict__ V,
          float* __restrict__ Ctx)
{
    extern __shared__ uint32_t sm[];
    uint32_t* Qf = sm;                          // A-frag: 8 ma x 8 kb
    uint32_t* Kf = sm + 64 * 132;               // B-frag: 8 na x 8 kb
    uint32_t* Vf = Kf + 64 * 66;                // B-frag: 8 na x 8 kb
    uint32_t* Pf = Vf + 64 * 66;                // per-warp A-frag: 1 ma x 8 kb

    const int tid  = threadIdx.x;
    const int lane = tid & 31, w = tid >> 5;
    const int lq = lane >> 2, lr = lane & 3;
    const int z = blockIdx.y, b = z >> 3, h = z & 7;
    const int i0 = blockIdx.x * 128;
    const int r0 = i0 + w * 16 + lq;
    const int r1 = r0 + 8;

    const float* Qb = Qu + ((size_t)(b * SS) + i0) * DD + h * DHH;
    const float* Kb = Km + (size_t)(b * SS) * DD + h * DHH;
    const float* Vb = V  + (size_t)(b * SS) * DD + h * DHH;
    const float* Mrow0 = M + ((size_t)z * SS + r0) * SS;
    const float* Mrow1 = M + ((size_t)z * SS + r1) * SS;
    uint32_t* Pw = Pf + w * (8 * 132);

    const float scale = 0.04419417382415922f;   // 1/sqrt(512)

    // resident Q tile [128 x 64] -> A-frag
#pragma unroll
    for (int t = 0; t < 8; t++) {
        int id = tid + t * 256;
        int row = id >> 4;
        int c4  = (id & 15) * 4;
        float4 q4 = *(const float4*)&Qb[(size_t)row * DD + c4];
        stA(Qf, 8, row, c4, q4);
    }

    float acc[8][4] = {};
    float rm0 = -1e30f, rm1 = -1e30f, l0 = 0.f, l1 = 0.f;

    for (int j0 = 0; j0 < SS; j0 += 64) {
        __syncthreads();   // WAR on Kf/Vf from previous iteration's MMAs
#pragma unroll
        for (int t = 0; t < 4; t++) {
            int id = tid + t * 256;
            int row = id >> 4;
            int c4  = (id & 15) * 4;
            float4 k4 = *(const float4*)&Kb[(size_t)(j0 + row) * DD + c4];
            stB_kquad(Kf, 8, row, c4, k4);               // (n=j, k=d)
            float4 v4 = *(const float4*)&Vb[(size_t)(j0 + row) * DD + c4];
            stB_nquad(Vf, 8, row, c4, v4);               // (k=j, n=d)
        }
        __syncthreads();

        // S = Q K^T  (warp: 16 rows x 64 j)
        float s[8][4] = {};
#pragma unroll
        for (int kb = 0; kb < 8; kb++) {
            uint32_t a[4];
            ldA(a, Qf, 8, w, kb, lane);
#pragma unroll
            for (int an = 0; an < 8; an++) {
                uint32_t b2[2];
                ldB(b2, Kf, 8, an, kb, lane);
                mma_tf32(s[an], a[0], a[1], a[2], a[3], b2[0], b2[1]);
            }
        }

        // add rel-shifted pos scores, scale, tile max
        float tm0 = -1e30f, tm1 = -1e30f;
#pragma unroll
        for (int an = 0; an < 8; an++) {
#pragma unroll
            for (int e = 0; e < 2; e++) {
                int j = j0 + an * 8 + 2 * lr + e;
                float pv0, pv1;
                if (j <= r0)          pv0 = Mrow0[SS - 1 - r0 + j];
                else if (j == r0 + 1) pv0 = 0.f;
                else                  pv0 = Mrow0[SS + (j - r0 - 2)];
                if (j <= r1)          pv1 = Mrow1[SS - 1 - r1 + j];
                else if (j == r1 + 1) pv1 = 0.f;
                else                  pv1 = Mrow1[SS + (j - r1 - 2)];
                float s0 = (s[an][e]     + pv0) * scale;
                float s1 = (s[an][2 + e] + pv1) * scale;
                s[an][e] = s0; s[an][2 + e] = s1;
                tm0 = fmaxf(tm0, s0); tm1 = fmaxf(tm1, s1);
            }
        }
        tm0 = fmaxf(tm0, __shfl_xor_sync(0xffffffffu, tm0, 1));
        tm0 = fmaxf(tm0, __shfl_xor_sync(0xffffffffu, tm0, 2));
        tm1 = fmaxf(tm1, __shfl_xor_sync(0xffffffffu, tm1, 1));
        tm1 = fmaxf(tm1, __shfl_xor_sync(0xffffffffu, tm1, 2));

        float nm0 = fmaxf(rm0, tm0), nm1 = fmaxf(rm1, tm1);
        float al0 = __expf(rm0 - nm0), al1 = __expf(rm1 - nm1);
        float sum0 = 0.f, sum1 = 0.f;
#pragma unroll
        for (int an = 0; an < 8; an++)
#pragma unroll
            for (int e = 0; e < 2; e++) {
                s[an][e]     = __expf(s[an][e]     - nm0); sum0 += s[an][e];
                s[an][2 + e] = __expf(s[an][2 + e] - nm1); sum1 += s[an][2 + e];
            }
        sum0 += __shfl_xor_sync(0xffffffffu, sum0, 1);
        sum0 += __shfl_xor_sync(0xffffffffu, sum0, 2);
        sum1 += __shfl_xor_sync(0xffffffffu, sum1, 1);
        sum1 += __shfl_xor_sync(0xffffffffu, sum1, 2);
        l0 = l0 * al0 + sum0; l1 = l1 * al1 + sum1;
        rm0 = nm0; rm1 = nm1;

#pragma unroll
        for (int an = 0; an < 8; an++) {
            acc[an][0] *= al0; acc[an][1] *= al0;
            acc[an][2] *= al1; acc[an][3] *= al1;
        }
        // P -> per-warp A-frag smem (rows lq / lq+8 are reg-adjacent -> STS.64)
#pragma unroll
        for (int an = 0; an < 8; an++) {
#pragma unroll
            for (int e = 0; e < 2; e++) {
                int c = 2 * lr + e;
                uint32_t* p = Pw + an * 132 + (4 * lq + (c & 3)) * 4 + 2 * ((c >> 2) & 1);
                *(uint2*)p = make_uint2(f2tf(s[an][e]), f2tf(s[an][2 + e]));
            }
        }
        __syncwarp();

        // O += P @ V
#pragma unroll
        for (int kb = 0; kb < 8; kb++) {
            uint32_t a[4];
            ldA(a, Pw, 8, 0, kb, lane);
#pragma unroll
            for (int an = 0; an < 8; an++) {
                uint32_t b2[2];
                ldB(b2, Vf, 8, an, kb, lane);
                mma_tf32(acc[an], a[0], a[1], a[2], a[3], b2[0], b2[1]);
            }
        }
    }

    float inv0 = 1.f / l0, inv1 = 1.f / l1;
#pragma unroll
    for (int an = 0; an < 8; an++) {
        int col = an * 8 + 2 * lr;
        float2 v0 = make_float2(acc[an][0] * inv0, acc[an][1] * inv0);
        float2 v1 = make_float2(acc[an][2] * inv1, acc[an][3] * inv1);
        *(float2*)&Ctx[(size_t)(b * SS + r0) * DD + h * DHH + col] = v0;
        *(float2*)&Ctx[(size_t)(b * SS + r1) * DD + h * DHH + col] = v1;
    }
}

// ---------------- launcher ------------------------------------------------------
extern "C" void kernel_launch(void* const* d_in, const int* in_sizes, int n_in,
                              void* d_out, int out_size)
{
    (void)in_sizes; (void)n_in; (void)out_size;
    const float* query = (const float*)d_in[0];
    const float* key   = (const float*)d_in[1];
    const float* value = (const float*)d_in[2];
    const float* pose  = (const float*)d_in[3];
    const float* Wq = (const float*)d_in[4];
    const float* bq = (const float*)d_in[5];
    const float* Wk = (const float*)d_in[6];
    const float* bk = (const float*)d_in[7];
    const float* Wv = (const float*)d_in[8];
    const float* bv = (const float*)d_in[9];
    const float* Wp = (const float*)d_in[10];
    const float* ub = (const float*)d_in[11];
    const float* vb = (const float*)d_in[12];
    const float* Wo = (const float*)d_in[13];
    const float* bo = (const float*)d_in[14];
    float* out = (float*)d_out;

    float *qu, *qv, *kk, *vv, *pp, *M, *ctx;
    cudaGetSymbolAddress((void**)&qu,  g_qu);
    cudaGetSymbolAddress((void**)&qv,  g_qv);
    cudaGetSymbolAddress((void**)&kk,  g_k);
    cudaGetSymbolAddress((void**)&vv,  g_v);
    cudaGetSymbolAddress((void**)&pp,  g_p);
    cudaGetSymbolAddress((void**)&M,   g_M);
    cudaGetSymbolAddress((void**)&ctx, g_ctx);

    cudaFuncSetAttribute(score_kernel, cudaFuncAttributeMaxDynamicSharedMemorySize,
                         SC_SMEM_BYTES);
    cudaFuncSetAttribute(fa_kernel, cudaFuncAttributeMaxDynamicSharedMemorySize,
                         FA_SMEM_BYTES);

    // merged 4 input projections
    ProjArgs pa;
    pa.s[0] = {query, Wq, bq, ub, vb, qu, qv};
    pa.s[1] = {key,   Wk, bk, nullptr, nullptr, kk, nullptr};
    pa.s[2] = {value, Wv, bv, nullptr, nullptr, vv, nullptr};
    pa.s[3] = {pose,  Wp, nullptr, nullptr, nullptr, pp, nullptr};
    dim3 pg(DD / 128, MTOT / 128, 4);      // (4, 64, 4)
    proj_kernel<<<pg, 256>>>(pa);

    dim3 sg(SS / 128, SS / 128, BH);       // (8,8,64)
    score_kernel<<<sg, 256, SC_SMEM_BYTES>>>(qv, pp, M);

    dim3 fg(SS / 128, BH);                 // (8, 64)
    fa_kernel<<<fg, 256, FA_SMEM_BYTES>>>(qu, kk, M, vv, ctx);

    // output projection
    ProjArgs po;
    po.s[0] = {ctx, Wo, bo, nullptr, nullptr, out, nullptr};
    po.s[1] = po.s[0]; po.s[2] = po.s[0]; po.s[3] = po.s[0];
    dim3 pg1(DD / 128, MTOT / 128, 1);     // (4, 64, 1)
    proj_kernel<<<pg1, 256>>>(po);
}

// round 7
// speedup vs baseline: 3.5662x; 1.6129x over previous
#include <cuda_runtime.h>
#include <cuda_fp16.h>
#include <cstdint>

#define BB 8
#define SS 1024
#define DD 512
#define HH 8
#define DHH 64
#define MTOT (BB*SS)   // 8192
#define BH   (BB*HH)   // 64

// ---------------- scratch (__device__ globals) ---------------------------------
__device__ float g_qu[MTOT*DD];                 // q + u_bias
__device__ float g_qv[MTOT*DD];                 // q + v_bias
__device__ float g_k [MTOT*DD];
__device__ float g_v [MTOT*DD];
__device__ float g_p [MTOT*DD];
__device__ float g_M [BH*SS*SS];                // pos scores pre-shift (fp32, 256 MB)
__device__ float g_ctx[MTOT*DD];

// ---------------- fp16 helpers --------------------------------------------------
__device__ __forceinline__ uint32_t h2u(float a, float b) {
    __half2 h = __floats2half2_rn(a, b);
    return *reinterpret_cast<uint32_t*>(&h);
}
__device__ __forceinline__ uint4 pack8(float4 a, float4 b) {
    uint4 r;
    r.x = h2u(a.x, a.y); r.y = h2u(a.z, a.w);
    r.z = h2u(b.x, b.y); r.w = h2u(b.z, b.w);
    return r;
}
__device__ __forceinline__ void ldsm4(uint32_t* r, const __half* p) {
    uint32_t a = (uint32_t)__cvta_generic_to_shared(p);
    asm volatile("ldmatrix.sync.aligned.m8n8.x4.shared.b16 {%0,%1,%2,%3}, [%4];"
                 : "=r"(r[0]), "=r"(r[1]), "=r"(r[2]), "=r"(r[3]) : "r"(a));
}
__device__ __forceinline__ void ldsm4t(uint32_t* r, const __half* p) {
    uint32_t a = (uint32_t)__cvta_generic_to_shared(p);
    asm volatile("ldmatrix.sync.aligned.m8n8.x4.trans.shared.b16 {%0,%1,%2,%3}, [%4];"
                 : "=r"(r[0]), "=r"(r[1]), "=r"(r[2]), "=r"(r[3]) : "r"(a));
}
__device__ __forceinline__ void mma_f16(float c[4], const uint32_t a[4],
                                        uint32_t b0, uint32_t b1)
{
    asm volatile(
        "mma.sync.aligned.m16n8k16.row.col.f32.f16.f16.f32 "
        "{%0,%1,%2,%3}, {%4,%5,%6,%7}, {%8,%9}, {%0,%1,%2,%3};"
        : "+f"(c[0]), "+f"(c[1]), "+f"(c[2]), "+f"(c[3])
        : "r"(a[0]), "r"(a[1]), "r"(a[2]), "r"(a[3]), "r"(b0), "r"(b1));
}

// ldmatrix lane-address components (mat = lane>>3):
//   A / trans-B rows:   aR = (mat&1)*8 + lane%8,  col add aK = (mat>>1)*8
//   non-trans B rows:   bR = (mat>>1)*8 + lane%8, col add bK = (mat&1)*8

// ---------------- kernel 1: projection GEMM (fp16, merged) ----------------------
struct ProjSet {
    const float *A, *W, *bias, *ex0, *ex1;
    float *out0, *out1;
};
struct ProjArgs { ProjSet s[4]; };

#define BFS 136   // W tile row stride in halves (128 cols + 8 pad, odd 16B chunks)

__global__ void __launch_bounds__(256, 2)
proj_kernel(ProjArgs args)
{
    __shared__ __half Af[128 * 40];    // A tile [m][k], rows padded to 40 halves
    __shared__ __half Bf[32 * BFS];    // W tile [k][n], n = 128 wide
    const ProjSet ps = args.s[blockIdx.z];
    const float* __restrict__ A = ps.A;
    const float* __restrict__ W = ps.W;

    const int tid  = threadIdx.x;
    const int lane = tid & 31, w = tid >> 5;
    const int wm = w & 1, wn = w >> 1;            // 2 x 4 warps, warp tile 64x32
    const int m_w = wm * 64, n_w = wn * 32;
    const int m0 = blockIdx.y * 128, n0 = blockIdx.x * 128;
    const int lq = lane >> 2, lr = lane & 3;
    const int aR = ((lane >> 3) & 1) * 8 + (lane & 7);
    const int aK = (lane >> 4) * 8;

    const int a_r = tid >> 2, a_c = (tid & 3) * 8;     // A: rows +t*64
    const int b_r = tid >> 4, b_c = (tid & 15) * 8;    // W: rows +t*16

    float4 pa[2][2], pb[2][2];
#pragma unroll
    for (int t = 0; t < 2; t++) {
        const float* p = &A[(size_t)(m0 + a_r + t * 64) * DD + a_c];
        pa[t][0] = *(const float4*)p; pa[t][1] = *(const float4*)(p + 4);
        const float* q = &W[(size_t)(b_r + t * 16) * DD + n0 + b_c];
        pb[t][0] = *(const float4*)q; pb[t][1] = *(const float4*)(q + 4);
    }

    float acc[4][4][4] = {};

    for (int k0 = 0; k0 < DD; k0 += 32) {
#pragma unroll
        for (int t = 0; t < 2; t++)
            *(uint4*)&Af[(a_r + t * 64) * 40 + a_c] = pack8(pa[t][0], pa[t][1]);
#pragma unroll
        for (int t = 0; t < 2; t++)
            *(uint4*)&Bf[(b_r + t * 16) * BFS + b_c] = pack8(pb[t][0], pb[t][1]);
        __syncthreads();
        if (k0 + 32 < DD) {
#pragma unroll
            for (int t = 0; t < 2; t++) {
                const float* p = &A[(size_t)(m0 + a_r + t * 64) * DD + k0 + 32 + a_c];
                pa[t][0] = *(const float4*)p; pa[t][1] = *(const float4*)(p + 4);
                const float* q = &W[(size_t)(k0 + 32 + b_r + t * 16) * DD + n0 + b_c];
                pb[t][0] = *(const float4*)q; pb[t][1] = *(const float4*)(q + 4);
            }
        }
#pragma unroll
        for (int kb = 0; kb < 2; kb++) {
            uint32_t a[4][4], bb[2][4];
#pragma unroll
            for (int ma = 0; ma < 4; ma++)
                ldsm4(a[ma], &Af[(m_w + ma * 16 + aR) * 40 + kb * 16 + aK]);
#pragma unroll
            for (int np = 0; np < 2; np++)
                ldsm4t(bb[np], &Bf[(kb * 16 + aR) * BFS + n_w + np * 16 + aK]);
#pragma unroll
            for (int ma = 0; ma < 4; ma++)
#pragma unroll
                for (int an = 0; an < 4; an++)
                    mma_f16(acc[ma][an], a[ma],
                            bb[an >> 1][(an & 1) * 2], bb[an >> 1][(an & 1) * 2 + 1]);
        }
        __syncthreads();
    }

#pragma unroll
    for (int ma = 0; ma < 4; ma++) {
#pragma unroll
        for (int an = 0; an < 4; an++) {
#pragma unroll
            for (int half = 0; half < 2; half++) {
                int row = m0 + m_w + ma * 16 + lq + half * 8;
                int col = n0 + n_w + an * 8 + lr * 2;
                float v0 = acc[ma][an][half * 2 + 0];
                float v1 = acc[ma][an][half * 2 + 1];
                if (ps.bias) { v0 += ps.bias[col]; v1 += ps.bias[col + 1]; }
                if (ps.out0) {
                    float e0 = ps.ex0 ? ps.ex0[col] : 0.f;
                    float e1 = ps.ex0 ? ps.ex0[col + 1] : 0.f;
                    float2 vv = make_float2(v0 + e0, v1 + e1);
                    *(float2*)&ps.out0[(size_t)row * DD + col] = vv;
                }
                if (ps.out1) {
                    float e0 = ps.ex1 ? ps.ex1[col] : 0.f;
                    float e1 = ps.ex1 ? ps.ex1[col + 1] : 0.f;
                    float2 vv = make_float2(v0 + e0, v1 + e1);
                    *(float2*)&ps.out1[(size_t)row * DD + col] = vv;
                }
            }
        }
    }
}

// ---------------- kernel 2: pos-score GEMM (M), fp16 ----------------------------
__global__ void __launch_bounds__(256, 2)
score_kernel(const float* __restrict__ Qm, const float* __restrict__ Km,
             float* __restrict__ Out)
{
    __shared__ __half Qf[128 * 72];    // [i][d], d = 64
    __shared__ __half Pf[128 * 72];    // [j][d]
    const int tid  = threadIdx.x;
    const int lane = tid & 31, w = tid >> 5;
    const int wm = w & 1, wn = w >> 1;
    const int m_w = wm * 64, n_w = wn * 32;
    const int z = blockIdx.z, b = z >> 3, h = z & 7;
    const int i0 = blockIdx.y * 128, j0 = blockIdx.x * 128;
    const int lq = lane >> 2, lr = lane & 3;
    const int aR = ((lane >> 3) & 1) * 8 + (lane & 7);
    const int aK = (lane >> 4) * 8;
    const int bR = (lane >> 4) * 8 + (lane & 7);
    const int bK = ((lane >> 3) & 1) * 8;
    const float* Qb = Qm + (size_t)(b * SS) * DD + h * DHH;
    const float* Kb = Km + (size_t)(b * SS) * DD + h * DHH;

#pragma unroll
    for (int t = 0; t < 4; t++) {
        int id = tid + t * 256;
        int row = id >> 3, col = (id & 7) * 8;
        const float* p = &Qb[(size_t)(i0 + row) * DD + col];
        *(uint4*)&Qf[row * 72 + col] = pack8(*(const float4*)p, *(const float4*)(p + 4));
        const float* q = &Kb[(size_t)(j0 + row) * DD + col];
        *(uint4*)&Pf[row * 72 + col] = pack8(*(const float4*)q, *(const float4*)(q + 4));
    }
    __syncthreads();

    float acc[4][4][4] = {};
#pragma unroll
    for (int kb = 0; kb < 4; kb++) {
        uint32_t a[4][4], bb[2][4];
#pragma unroll
        for (int ma = 0; ma < 4; ma++)
            ldsm4(a[ma], &Qf[(m_w + ma * 16 + aR) * 72 + kb * 16 + aK]);
#pragma unroll
        for (int np = 0; np < 2; np++)
            ldsm4(bb[np], &Pf[(n_w + np * 16 + bR) * 72 + kb * 16 + bK]);
#pragma unroll
        for (int ma = 0; ma < 4; ma++)
#pragma unroll
            for (int an = 0; an < 4; an++)
                mma_f16(acc[ma][an], a[ma],
                        bb[an >> 1][(an & 1) * 2], bb[an >> 1][(an & 1) * 2 + 1]);
    }

#pragma unroll
    for (int ma = 0; ma < 4; ma++) {
#pragma unroll
        for (int an = 0; an < 4; an++) {
#pragma unroll
            for (int half = 0; half < 2; half++) {
                int row = i0 + m_w + ma * 16 + lq + half * 8;
                int col = j0 + n_w + an * 8 + lr * 2;
                float2 vv = make_float2(acc[ma][an][half * 2 + 0],
                                        acc[ma][an][half * 2 + 1]);
                *(float2*)&Out[((size_t)z * SS + row) * SS + col] = vv;
            }
        }
    }
}

// ---------------- kernel 3: fused QK^T + shift + softmax + PV -------------------
// 128 thr = 4 warps; block owns 64 q-rows; warp owns 16. P stays in registers.
__global__ void __launch_bounds__(128, 4)
fa_kernel(const float* __restrict__ Qu, const float* __restrict__ Km,
          const float* __restrict__ M, const float* __restrict__ V,
          float* __restrict__ Ctx)
{
    __shared__ __half Qf[64 * 72];     // [i][d]
    __shared__ __half Kf[64 * 72];     // [j][d]
    __shared__ __half Vf[64 * 72];     // [j][d]

    const int tid  = threadIdx.x;
    const int lane = tid & 31, w = tid >> 5;
    const int lq = lane >> 2, lr = lane & 3;
    const int aR = ((lane >> 3) & 1) * 8 + (lane & 7);
    const int aK = (lane >> 4) * 8;
    const int bR = (lane >> 4) * 8 + (lane & 7);
    const int bK = ((lane >> 3) & 1) * 8;
    const int z = blockIdx.y, b = z >> 3, h = z & 7;
    const int i0 = blockIdx.x * 64;
    const int r0 = i0 + w * 16 + lq;
    const int r1 = r0 + 8;

    const float* Qb = Qu + ((size_t)(b * SS) + i0) * DD + h * DHH;
    const float* Kb = Km + (size_t)(b * SS) * DD + h * DHH;
    const float* Vb = V  + (size_t)(b * SS) * DD + h * DHH;
    const float* Mrow0 = M + ((size_t)z * SS + r0) * SS;
    const float* Mrow1 = M + ((size_t)z * SS + r1) * SS;

    const float scale = 0.04419417382415922f;   // 1/sqrt(512)

    const int l_r = tid >> 3, l_c = (tid & 7) * 8;   // loader: rows +t*16

    // resident Q tile [64 x 64]
#pragma unroll
    for (int t = 0; t < 4; t++) {
        int row = l_r + t * 16;
        const float* p = &Qb[(size_t)row * DD + l_c];
        *(uint4*)&Qf[row * 72 + l_c] = pack8(*(const float4*)p, *(const float4*)(p + 4));
    }

    float acc[8][4] = {};
    float rm0 = -1e30f, rm1 = -1e30f, l0 = 0.f, l1 = 0.f;

    for (int jt = 0; jt < SS; jt += 64) {
        __syncthreads();   // WAR on Kf/Vf (and orders Q stores on iter 0)
#pragma unroll
        for (int t = 0; t < 4; t++) {
            int row = l_r + t * 16;
            const float* p = &Kb[(size_t)(jt + row) * DD + l_c];
            *(uint4*)&Kf[row * 72 + l_c] = pack8(*(const float4*)p, *(const float4*)(p + 4));
            const float* q = &Vb[(size_t)(jt + row) * DD + l_c];
            *(uint4*)&Vf[row * 72 + l_c] = pack8(*(const float4*)q, *(const float4*)(q + 4));
        }
        __syncthreads();

        // S = Q K^T  (warp: 16 rows x 64 j)
        float s[8][4] = {};
#pragma unroll
        for (int kb = 0; kb < 4; kb++) {
            uint32_t a[4], bb[4][4];
            ldsm4(a, &Qf[(w * 16 + aR) * 72 + kb * 16 + aK]);
#pragma unroll
            for (int np = 0; np < 4; np++)
                ldsm4(bb[np], &Kf[(np * 16 + bR) * 72 + kb * 16 + bK]);
#pragma unroll
            for (int an = 0; an < 8; an++)
                mma_f16(s[an], a,
                        bb[an >> 1][(an & 1) * 2], bb[an >> 1][(an & 1) * 2 + 1]);
        }

        // rel-shifted pos add, scale, tile max
        float tm0 = -1e30f, tm1 = -1e30f;
#pragma unroll
        for (int an = 0; an < 8; an++) {
#pragma unroll
            for (int e = 0; e < 2; e++) {
                int j = jt + an * 8 + 2 * lr + e;
                float pv0, pv1;
                if (j <= r0)          pv0 = Mrow0[SS - 1 - r0 + j];
                else if (j == r0 + 1) pv0 = 0.f;
                else                  pv0 = Mrow0[SS + (j - r0 - 2)];
                if (j <= r1)          pv1 = Mrow1[SS - 1 - r1 + j];
                else if (j == r1 + 1) pv1 = 0.f;
                else                  pv1 = Mrow1[SS + (j - r1 - 2)];
                float s0 = (s[an][e]     + pv0) * scale;
                float s1 = (s[an][2 + e] + pv1) * scale;
                s[an][e] = s0; s[an][2 + e] = s1;
                tm0 = fmaxf(tm0, s0); tm1 = fmaxf(tm1, s1);
            }
        }
        tm0 = fmaxf(tm0, __shfl_xor_sync(0xffffffffu, tm0, 1));
        tm0 = fmaxf(tm0, __shfl_xor_sync(0xffffffffu, tm0, 2));
        tm1 = fmaxf(tm1, __shfl_xor_sync(0xffffffffu, tm1, 1));
        tm1 = fmaxf(tm1, __shfl_xor_sync(0xffffffffu, tm1, 2));

        float nm0 = fmaxf(rm0, tm0), nm1 = fmaxf(rm1, tm1);
        float al0 = __expf(rm0 - nm0), al1 = __expf(rm1 - nm1);
        float sum0 = 0.f, sum1 = 0.f;
#pragma unroll
        for (int an = 0; an < 8; an++)
#pragma unroll
            for (int e = 0; e < 2; e++) {
                s[an][e]     = __expf(s[an][e]     - nm0); sum0 += s[an][e];
                s[an][2 + e] = __expf(s[an][2 + e] - nm1); sum1 += s[an][2 + e];
            }
        sum0 += __shfl_xor_sync(0xffffffffu, sum0, 1);
        sum0 += __shfl_xor_sync(0xffffffffu, sum0, 2);
        sum1 += __shfl_xor_sync(0xffffffffu, sum1, 1);
        sum1 += __shfl_xor_sync(0xffffffffu, sum1, 2);
        l0 = l0 * al0 + sum0; l1 = l1 * al1 + sum1;
        rm0 = nm0; rm1 = nm1;

#pragma unroll
        for (int an = 0; an < 8; an++) {
            acc[an][0] *= al0; acc[an][1] *= al0;
            acc[an][2] *= al1; acc[an][3] *= al1;
        }

        // O += P @ V ; P taken straight from registers (C-frag == A-frag layout)
#pragma unroll
        for (int jj = 0; jj < 4; jj++) {
            uint32_t a[4];
            a[0] = h2u(s[2*jj][0],     s[2*jj][1]);
            a[1] = h2u(s[2*jj][2],     s[2*jj][3]);
            a[2] = h2u(s[2*jj + 1][0], s[2*jj + 1][1]);
            a[3] = h2u(s[2*jj + 1][2], s[2*jj + 1][3]);
            uint32_t vv[4][4];
#pragma unroll
            for (int dp = 0; dp < 4; dp++)
                ldsm4t(vv[dp], &Vf[(jj * 16 + aR) * 72 + dp * 16 + aK]);
#pragma unroll
            for (int dn = 0; dn < 8; dn++)
                mma_f16(acc[dn], a,
                        vv[dn >> 1][(dn & 1) * 2], vv[dn >> 1][(dn & 1) * 2 + 1]);
        }
    }

    float inv0 = 1.f / l0, inv1 = 1.f / l1;
#pragma unroll
    for (int dn = 0; dn < 8; dn++) {
        int col = dn * 8 + 2 * lr;
        float2 v0 = make_float2(acc[dn][0] * inv0, acc[dn][1] * inv0);
        float2 v1 = make_float2(acc[dn][2] * inv1, acc[dn][3] * inv1);
        *(float2*)&Ctx[(size_t)(b * SS + r0) * DD + h * DHH + col] = v0;
        *(float2*)&Ctx[(size_t)(b * SS + r1) * DD + h * DHH + col] = v1;
    }
}

// ---------------- launcher ------------------------------------------------------
extern "C" void kernel_launch(void* const* d_in, const int* in_sizes, int n_in,
                              void* d_out, int out_size)
{
    (void)in_sizes; (void)n_in; (void)out_size;
    const float* query = (const float*)d_in[0];
    const float* key   = (const float*)d_in[1];
    const float* value = (const float*)d_in[2];
    const float* pose  = (const float*)d_in[3];
    const float* Wq = (const float*)d_in[4];
    const float* bq = (const float*)d_in[5];
    const float* Wk = (const float*)d_in[6];
    const float* bk = (const float*)d_in[7];
    const float* Wv = (const float*)d_in[8];
    const float* bv = (const float*)d_in[9];
    const float* Wp = (const float*)d_in[10];
    const float* ub = (const float*)d_in[11];
    const float* vb = (const float*)d_in[12];
    const float* Wo = (const float*)d_in[13];
    const float* bo = (const float*)d_in[14];
    float* out = (float*)d_out;

    float *qu, *qv, *kk, *vv, *pp, *M, *ctx;
    cudaGetSymbolAddress((void**)&qu,  g_qu);
    cudaGetSymbolAddress((void**)&qv,  g_qv);
    cudaGetSymbolAddress((void**)&kk,  g_k);
    cudaGetSymbolAddress((void**)&vv,  g_v);
    cudaGetSymbolAddress((void**)&pp,  g_p);
    cudaGetSymbolAddress((void**)&M,   g_M);
    cudaGetSymbolAddress((void**)&ctx, g_ctx);

    // merged 4 input projections
    ProjArgs pa;
    pa.s[0] = {query, Wq, bq, ub, vb, qu, qv};
    pa.s[1] = {key,   Wk, bk, nullptr, nullptr, kk, nullptr};
    pa.s[2] = {value, Wv, bv, nullptr, nullptr, vv, nullptr};
    pa.s[3] = {pose,  Wp, nullptr, nullptr, nullptr, pp, nullptr};
    dim3 pg(DD / 128, MTOT / 128, 4);      // (4, 64, 4)
    proj_kernel<<<pg, 256>>>(pa);

    dim3 sg(SS / 128, SS / 128, BH);       // (8,8,64)
    score_kernel<<<sg, 256>>>(qv, pp, M);

    dim3 fg(SS / 64, BH);                  // (16, 64)
    fa_kernel<<<fg, 128>>>(qu, kk, M, vv, ctx);

    // output projection
    ProjArgs po;
    po.s[0] = {ctx, Wo, bo, nullptr, nullptr, out, nullptr};
    po.s[1] = po.s[0]; po.s[2] = po.s[0]; po.s[3] = po.s[0];
    dim3 pg1(DD / 128, MTOT / 128, 1);     // (4, 64, 1)
    proj_kernel<<<pg1, 256>>>(po);
}

// round 8
// speedup vs baseline: 5.2536x; 1.4732x over previous
#include <cuda_runtime.h>
#include <cuda_fp16.h>
#include <cstdint>

#define BB 8
#define SS 1024
#define DD 512
#define HH 8
#define DHH 64
#define MTOT (BB*SS)   // 8192
#define BH   (BB*HH)   // 64

// ---------------- scratch (__device__ globals) ---------------------------------
__device__ __half g_qu[MTOT*DD];                // q + u_bias  (fp16)
__device__ __half g_qv[MTOT*DD];                // q + v_bias  (fp16)
__device__ __half g_k [MTOT*DD];
__device__ __half g_v [MTOT*DD];
__device__ __half g_p [MTOT*DD];
__device__ float  g_M [BH*SS*SS];               // pos scores pre-shift (fp32)
__device__ float  g_ctx[MTOT*DD];

// ---------------- helpers -------------------------------------------------------
__device__ __forceinline__ uint32_t h2u(float a, float b) {
    __half2 h = __floats2half2_rn(a, b);
    return *reinterpret_cast<uint32_t*>(&h);
}
__device__ __forceinline__ uint4 pack8(float4 a, float4 b) {
    uint4 r;
    r.x = h2u(a.x, a.y); r.y = h2u(a.z, a.w);
    r.z = h2u(b.x, b.y); r.w = h2u(b.z, b.w);
    return r;
}
__device__ __forceinline__ void ldsm4(uint32_t* r, const __half* p) {
    uint32_t a = (uint32_t)__cvta_generic_to_shared(p);
    asm volatile("ldmatrix.sync.aligned.m8n8.x4.shared.b16 {%0,%1,%2,%3}, [%4];"
                 : "=r"(r[0]), "=r"(r[1]), "=r"(r[2]), "=r"(r[3]) : "r"(a));
}
__device__ __forceinline__ void ldsm4t(uint32_t* r, const __half* p) {
    uint32_t a = (uint32_t)__cvta_generic_to_shared(p);
    asm volatile("ldmatrix.sync.aligned.m8n8.x4.trans.shared.b16 {%0,%1,%2,%3}, [%4];"
                 : "=r"(r[0]), "=r"(r[1]), "=r"(r[2]), "=r"(r[3]) : "r"(a));
}
__device__ __forceinline__ void mma_f16(float c[4], const uint32_t a[4],
                                        uint32_t b0, uint32_t b1)
{
    asm volatile(
        "mma.sync.aligned.m16n8k16.row.col.f32.f16.f16.f32 "
        "{%0,%1,%2,%3}, {%4,%5,%6,%7}, {%8,%9}, {%0,%1,%2,%3};"
        : "+f"(c[0]), "+f"(c[1]), "+f"(c[2]), "+f"(c[3])
        : "r"(a[0]), "r"(a[1]), "r"(a[2]), "r"(a[3]), "r"(b0), "r"(b1));
}
__device__ __forceinline__ void cpa16(__half* dst, const __half* src) {
    uint32_t d = (uint32_t)__cvta_generic_to_shared(dst);
    asm volatile("cp.async.ca.shared.global [%0], [%1], 16;" :: "r"(d), "l"(src));
}
#define CPA_COMMIT() asm volatile("cp.async.commit_group;")
#define CPA_WAIT0()  asm volatile("cp.async.wait_group 0;")

// ldmatrix lane-address components (mat = lane>>3):
//   A / trans-B rows:   aR = (mat&1)*8 + lane%8,  col add aK = (mat>>1)*8
//   non-trans B rows:   bR = (mat>>1)*8 + lane%8, col add bK = (mat&1)*8

// ---------------- kernel 1: projection GEMM (fp16 MMA, merged) ------------------
struct ProjSet {
    const float *A, *W, *bias, *ex0, *ex1;
    void *out0, *out1;     // __half* if h_out else float*
    int h_out;
};
struct ProjArgs { ProjSet s[4]; };

#define BFS 136   // W tile row stride in halves

__global__ void __launch_bounds__(256, 2)
proj_kernel(ProjArgs args)
{
    __shared__ __half Af[128 * 40];    // A tile [m][k]
    __shared__ __half Bf[32 * BFS];    // W tile [k][n], n = 128
    const ProjSet ps = args.s[blockIdx.z];
    const float* __restrict__ A = ps.A;
    const float* __restrict__ W = ps.W;

    const int tid  = threadIdx.x;
    const int lane = tid & 31, w = tid >> 5;
    const int wm = w & 1, wn = w >> 1;            // 2 x 4 warps, warp tile 64x32
    const int m_w = wm * 64, n_w = wn * 32;
    const int m0 = blockIdx.y * 128, n0 = blockIdx.x * 128;
    const int lq = lane >> 2, lr = lane & 3;
    const int aR = ((lane >> 3) & 1) * 8 + (lane & 7);
    const int aK = (lane >> 4) * 8;

    const int a_r = tid >> 2, a_c = (tid & 3) * 8;     // A: rows +t*64
    const int b_r = tid >> 4, b_c = (tid & 15) * 8;    // W: rows +t*16

    float4 pa[2][2], pb[2][2];
#pragma unroll
    for (int t = 0; t < 2; t++) {
        const float* p = &A[(size_t)(m0 + a_r + t * 64) * DD + a_c];
        pa[t][0] = *(const float4*)p; pa[t][1] = *(const float4*)(p + 4);
        const float* q = &W[(size_t)(b_r + t * 16) * DD + n0 + b_c];
        pb[t][0] = *(const float4*)q; pb[t][1] = *(const float4*)(q + 4);
    }

    float acc[4][4][4] = {};

    for (int k0 = 0; k0 < DD; k0 += 32) {
#pragma unroll
        for (int t = 0; t < 2; t++)
            *(uint4*)&Af[(a_r + t * 64) * 40 + a_c] = pack8(pa[t][0], pa[t][1]);
#pragma unroll
        for (int t = 0; t < 2; t++)
            *(uint4*)&Bf[(b_r + t * 16) * BFS + b_c] = pack8(pb[t][0], pb[t][1]);
        __syncthreads();
        if (k0 + 32 < DD) {
#pragma unroll
            for (int t = 0; t < 2; t++) {
                const float* p = &A[(size_t)(m0 + a_r + t * 64) * DD + k0 + 32 + a_c];
                pa[t][0] = *(const float4*)p; pa[t][1] = *(const float4*)(p + 4);
                const float* q = &W[(size_t)(k0 + 32 + b_r + t * 16) * DD + n0 + b_c];
                pb[t][0] = *(const float4*)q; pb[t][1] = *(const float4*)(q + 4);
            }
        }
#pragma unroll
        for (int kb = 0; kb < 2; kb++) {
            uint32_t a[4][4], bb[2][4];
#pragma unroll
            for (int ma = 0; ma < 4; ma++)
                ldsm4(a[ma], &Af[(m_w + ma * 16 + aR) * 40 + kb * 16 + aK]);
#pragma unroll
            for (int np = 0; np < 2; np++)
                ldsm4t(bb[np], &Bf[(kb * 16 + aR) * BFS + n_w + np * 16 + aK]);
#pragma unroll
            for (int ma = 0; ma < 4; ma++)
#pragma unroll
                for (int an = 0; an < 4; an++)
                    mma_f16(acc[ma][an], a[ma],
                            bb[an >> 1][(an & 1) * 2], bb[an >> 1][(an & 1) * 2 + 1]);
        }
        __syncthreads();
    }

#pragma unroll
    for (int ma = 0; ma < 4; ma++) {
#pragma unroll
        for (int an = 0; an < 4; an++) {
#pragma unroll
            for (int half = 0; half < 2; half++) {
                int row = m0 + m_w + ma * 16 + lq + half * 8;
                int col = n0 + n_w + an * 8 + lr * 2;
                float v0 = acc[ma][an][half * 2 + 0];
                float v1 = acc[ma][an][half * 2 + 1];
                if (ps.bias) { v0 += ps.bias[col]; v1 += ps.bias[col + 1]; }
                if (ps.out0) {
                    float e0 = ps.ex0 ? ps.ex0[col] : 0.f;
                    float e1 = ps.ex0 ? ps.ex0[col + 1] : 0.f;
                    if (ps.h_out)
                        *(uint32_t*)&((__half*)ps.out0)[(size_t)row * DD + col] =
                            h2u(v0 + e0, v1 + e1);
                    else
                        *(float2*)&((float*)ps.out0)[(size_t)row * DD + col] =
                            make_float2(v0 + e0, v1 + e1);
                }
                if (ps.out1) {
                    float e0 = ps.ex1 ? ps.ex1[col] : 0.f;
                    float e1 = ps.ex1 ? ps.ex1[col + 1] : 0.f;
                    *(uint32_t*)&((__half*)ps.out1)[(size_t)row * DD + col] =
                        h2u(v0 + e0, v1 + e1);
                }
            }
        }
    }
}

// ---------------- kernel 2: pos-score GEMM (M), fp16 inputs ---------------------
__global__ void __launch_bounds__(256, 2)
score_kernel(const __half* __restrict__ Qm, const __half* __restrict__ Km,
             float* __restrict__ Out)
{
    __shared__ __half Qf[128 * 72];    // [i][d]
    __shared__ __half Pf[128 * 72];    // [j][d]
    const int tid  = threadIdx.x;
    const int lane = tid & 31, w = tid >> 5;
    const int wm = w & 1, wn = w >> 1;
    const int m_w = wm * 64, n_w = wn * 32;
    const int z = blockIdx.z, b = z >> 3, h = z & 7;
    const int i0 = blockIdx.y * 128, j0 = blockIdx.x * 128;
    const int lq = lane >> 2, lr = lane & 3;
    const int aR = ((lane >> 3) & 1) * 8 + (lane & 7);
    const int aK = (lane >> 4) * 8;
    const int bR = (lane >> 4) * 8 + (lane & 7);
    const int bK = ((lane >> 3) & 1) * 8;
    const __half* Qb = Qm + (size_t)(b * SS) * DD + h * DHH;
    const __half* Kb = Km + (size_t)(b * SS) * DD + h * DHH;

#pragma unroll
    for (int t = 0; t < 4; t++) {
        int id = tid + t * 256;
        int row = id >> 3, col = (id & 7) * 8;
        *(uint4*)&Qf[row * 72 + col] = *(const uint4*)&Qb[(size_t)(i0 + row) * DD + col];
        *(uint4*)&Pf[row * 72 + col] = *(const uint4*)&Kb[(size_t)(j0 + row) * DD + col];
    }
    __syncthreads();

    float acc[4][4][4] = {};
#pragma unroll
    for (int kb = 0; kb < 4; kb++) {
        uint32_t a[4][4], bb[2][4];
#pragma unroll
        for (int ma = 0; ma < 4; ma++)
            ldsm4(a[ma], &Qf[(m_w + ma * 16 + aR) * 72 + kb * 16 + aK]);
#pragma unroll
        for (int np = 0; np < 2; np++)
            ldsm4(bb[np], &Pf[(n_w + np * 16 + bR) * 72 + kb * 16 + bK]);
#pragma unroll
        for (int ma = 0; ma < 4; ma++)
#pragma unroll
            for (int an = 0; an < 4; an++)
                mma_f16(acc[ma][an], a[ma],
                        bb[an >> 1][(an & 1) * 2], bb[an >> 1][(an & 1) * 2 + 1]);
    }

#pragma unroll
    for (int ma = 0; ma < 4; ma++) {
#pragma unroll
        for (int an = 0; an < 4; an++) {
#pragma unroll
            for (int half = 0; half < 2; half++) {
                int row = i0 + m_w + ma * 16 + lq + half * 8;
                int col = j0 + n_w + an * 8 + lr * 2;
                float2 vv = make_float2(acc[ma][an][half * 2 + 0],
                                        acc[ma][an][half * 2 + 1]);
                *(float2*)&Out[((size_t)z * SS + row) * SS + col] = vv;
            }
        }
    }
}

// ---------------- kernel 3: fused QK^T + shift + softmax + PV -------------------
// 128 thr = 4 warps; block owns 64 q-rows. cp.async double-buffered K/V;
// M band prefetched into regs ahead of the QK MMAs; P stays in registers.
__global__ void __launch_bounds__(128, 3)
fa_kernel(const __half* __restrict__ Qu, const __half* __restrict__ Km,
          const float* __restrict__ M, const __half* __restrict__ V,
          float* __restrict__ Ctx)
{
    __shared__ __half Qf[64 * 72];
    __shared__ __half Kf[2][64 * 72];
    __shared__ __half Vf[2][64 * 72];

    const int tid  = threadIdx.x;
    const int lane = tid & 31, w = tid >> 5;
    const int lq = lane >> 2, lr = lane & 3;
    const int aR = ((lane >> 3) & 1) * 8 + (lane & 7);
    const int aK = (lane >> 4) * 8;
    const int bR = (lane >> 4) * 8 + (lane & 7);
    const int bK = ((lane >> 3) & 1) * 8;
    const int z = blockIdx.y, b = z >> 3, h = z & 7;
    const int i0 = blockIdx.x * 64;
    const int r0 = i0 + w * 16 + lq;
    const int r1 = r0 + 8;

    const __half* Qb = Qu + ((size_t)(b * SS) + i0) * DD + h * DHH;
    const __half* Kb = Km + (size_t)(b * SS) * DD + h * DHH;
    const __half* Vb = V  + (size_t)(b * SS) * DD + h * DHH;
    const float* Mrow0 = M + ((size_t)z * SS + r0) * SS;
    const float* Mrow1 = M + ((size_t)z * SS + r1) * SS;

    const float scale = 0.04419417382415922f;   // 1/sqrt(512)

    // cp.async loader mapping: 512 16B-chunks per 64x64 tile, 4 per thread
    const int c_row = tid >> 1;                 // 0..63 (t adds 0; id = tid + t*128)
    // initial group: Q + K0 + V0
#pragma unroll
    for (int t = 0; t < 4; t++) {
        int id = tid + t * 128;
        int row = id >> 3, ch = (id & 7) * 8;
        cpa16(&Qf[row * 72 + ch],    &Qb[(size_t)row * DD + ch]);
        cpa16(&Kf[0][row * 72 + ch], &Kb[(size_t)row * DD + ch]);
        cpa16(&Vf[0][row * 72 + ch], &Vb[(size_t)row * DD + ch]);
    }
    CPA_COMMIT();
    (void)c_row;

    float acc[8][4] = {};
    float rm0 = -1e30f, rm1 = -1e30f, l0 = 0.f, l1 = 0.f;
    int buf = 0;

    for (int jt = 0; jt < SS; jt += 64) {
        // prefetch M band for this tile (consumed after the QK MMAs)
        float pv[8][4];
#pragma unroll
        for (int an = 0; an < 8; an++) {
#pragma unroll
            for (int e = 0; e < 2; e++) {
                int j = jt + an * 8 + 2 * lr + e;
                float p0, p1;
                if (j <= r0)          p0 = Mrow0[SS - 1 - r0 + j];
                else if (j == r0 + 1) p0 = 0.f;
                else                  p0 = Mrow0[SS + (j - r0 - 2)];
                if (j <= r1)          p1 = Mrow1[SS - 1 - r1 + j];
                else if (j == r1 + 1) p1 = 0.f;
                else                  p1 = Mrow1[SS + (j - r1 - 2)];
                pv[an][e] = p0; pv[an][2 + e] = p1;
            }
        }

        CPA_WAIT0();
        __syncthreads();           // all warps done with buf^1 reads + copies visible

        // kick off next tile's K/V copy into the other buffer
        if (jt + 64 < SS) {
            int nb = buf ^ 1;
#pragma unroll
            for (int t = 0; t < 4; t++) {
                int id = tid + t * 128;
                int row = id >> 3, ch = (id & 7) * 8;
                cpa16(&Kf[nb][row * 72 + ch], &Kb[(size_t)(jt + 64 + row) * DD + ch]);
                cpa16(&Vf[nb][row * 72 + ch], &Vb[(size_t)(jt + 64 + row) * DD + ch]);
            }
        }
        CPA_COMMIT();

        // S = Q K^T  (warp: 16 rows x 64 j)
        float s[8][4] = {};
#pragma unroll
        for (int kb = 0; kb < 4; kb++) {
            uint32_t a[4], bb[4][4];
            ldsm4(a, &Qf[(w * 16 + aR) * 72 + kb * 16 + aK]);
#pragma unroll
            for (int np = 0; np < 4; np++)
                ldsm4(bb[np], &Kf[buf][(np * 16 + bR) * 72 + kb * 16 + bK]);
#pragma unroll
            for (int an = 0; an < 8; an++)
                mma_f16(s[an], a,
                        bb[an >> 1][(an & 1) * 2], bb[an >> 1][(an & 1) * 2 + 1]);
        }

        // combine with pos scores, scale, tile max
        float tm0 = -1e30f, tm1 = -1e30f;
#pragma unroll
        for (int an = 0; an < 8; an++) {
#pragma unroll
            for (int e = 0; e < 2; e++) {
                float s0 = (s[an][e]     + pv[an][e])     * scale;
                float s1 = (s[an][2 + e] + pv[an][2 + e]) * scale;
                s[an][e] = s0; s[an][2 + e] = s1;
                tm0 = fmaxf(tm0, s0); tm1 = fmaxf(tm1, s1);
            }
        }
        tm0 = fmaxf(tm0, __shfl_xor_sync(0xffffffffu, tm0, 1));
        tm0 = fmaxf(tm0, __shfl_xor_sync(0xffffffffu, tm0, 2));
        tm1 = fmaxf(tm1, __shfl_xor_sync(0xffffffffu, tm1, 1));
        tm1 = fmaxf(tm1, __shfl_xor_sync(0xffffffffu, tm1, 2));

        float nm0 = fmaxf(rm0, tm0), nm1 = fmaxf(rm1, tm1);
        float al0 = __expf(rm0 - nm0), al1 = __expf(rm1 - nm1);
        float sum0 = 0.f, sum1 = 0.f;
#pragma unroll
        for (int an = 0; an < 8; an++)
#pragma unroll
            for (int e = 0; e < 2; e++) {
                s[an][e]     = __expf(s[an][e]     - nm0); sum0 += s[an][e];
                s[an][2 + e] = __expf(s[an][2 + e] - nm1); sum1 += s[an][2 + e];
            }
        sum0 += __shfl_xor_sync(0xffffffffu, sum0, 1);
        sum0 += __shfl_xor_sync(0xffffffffu, sum0, 2);
        sum1 += __shfl_xor_sync(0xffffffffu, sum1, 1);
        sum1 += __shfl_xor_sync(0xffffffffu, sum1, 2);
        l0 = l0 * al0 + sum0; l1 = l1 * al1 + sum1;
        rm0 = nm0; rm1 = nm1;

#pragma unroll
        for (int an = 0; an < 8; an++) {
            acc[an][0] *= al0; acc[an][1] *= al0;
            acc[an][2] *= al1; acc[an][3] *= al1;
        }

        // O += P @ V ; P straight from registers (C-frag == A-frag layout)
#pragma unroll
        for (int jj = 0; jj < 4; jj++) {
            uint32_t a[4];
            a[0] = h2u(s[2*jj][0],     s[2*jj][1]);
            a[1] = h2u(s[2*jj][2],     s[2*jj][3]);
            a[2] = h2u(s[2*jj + 1][0], s[2*jj + 1][1]);
            a[3] = h2u(s[2*jj + 1][2], s[2*jj + 1][3]);
            uint32_t vv[4][4];
#pragma unroll
            for (int dp = 0; dp < 4; dp++)
                ldsm4t(vv[dp], &Vf[buf][(jj * 16 + aR) * 72 + dp * 16 + aK]);
#pragma unroll
            for (int dn = 0; dn < 8; dn++)
                mma_f16(acc[dn], a,
                        vv[dn >> 1][(dn & 1) * 2], vv[dn >> 1][(dn & 1) * 2 + 1]);
        }
        buf ^= 1;
    }

    float inv0 = 1.f / l0, inv1 = 1.f / l1;
#pragma unroll
    for (int dn = 0; dn < 8; dn++) {
        int col = dn * 8 + 2 * lr;
        float2 v0 = make_float2(acc[dn][0] * inv0, acc[dn][1] * inv0);
        float2 v1 = make_float2(acc[dn][2] * inv1, acc[dn][3] * inv1);
        *(float2*)&Ctx[(size_t)(b * SS + r0) * DD + h * DHH + col] = v0;
        *(float2*)&Ctx[(size_t)(b * SS + r1) * DD + h * DHH + col] = v1;
    }
}

// ---------------- launcher ------------------------------------------------------
extern "C" void kernel_launch(void* const* d_in, const int* in_sizes, int n_in,
                              void* d_out, int out_size)
{
    (void)in_sizes; (void)n_in; (void)out_size;
    const float* query = (const float*)d_in[0];
    const float* key   = (const float*)d_in[1];
    const float* value = (const float*)d_in[2];
    const float* pose  = (const float*)d_in[3];
    const float* Wq = (const float*)d_in[4];
    const float* bq = (const float*)d_in[5];
    const float* Wk = (const float*)d_in[6];
    const float* bk = (const float*)d_in[7];
    const float* Wv = (const float*)d_in[8];
    const float* bv = (const float*)d_in[9];
    const float* Wp = (const float*)d_in[10];
    const float* ub = (const float*)d_in[11];
    const float* vb = (const float*)d_in[12];
    const float* Wo = (const float*)d_in[13];
    const float* bo = (const float*)d_in[14];
    float* out = (float*)d_out;

    __half *qu, *qv, *kk, *vv, *pp;
    float *M, *ctx;
    cudaGetSymbolAddress((void**)&qu,  g_qu);
    cudaGetSymbolAddress((void**)&qv,  g_qv);
    cudaGetSymbolAddress((void**)&kk,  g_k);
    cudaGetSymbolAddress((void**)&vv,  g_v);
    cudaGetSymbolAddress((void**)&pp,  g_p);
    cudaGetSymbolAddress((void**)&M,   g_M);
    cudaGetSymbolAddress((void**)&ctx, g_ctx);

    // merged 4 input projections (fp16 outputs)
    ProjArgs pa;
    pa.s[0] = {query, Wq, bq, ub, vb, qu, qv, 1};
    pa.s[1] = {key,   Wk, bk, nullptr, nullptr, kk, nullptr, 1};
    pa.s[2] = {value, Wv, bv, nullptr, nullptr, vv, nullptr, 1};
    pa.s[3] = {pose,  Wp, nullptr, nullptr, nullptr, pp, nullptr, 1};
    dim3 pg(DD / 128, MTOT / 128, 4);      // (4, 64, 4)
    proj_kernel<<<pg, 256>>>(pa);

    dim3 sg(SS / 128, SS / 128, BH);       // (8,8,64)
    score_kernel<<<sg, 256>>>(qv, pp, M);

    dim3 fg(SS / 64, BH);                  // (16, 64)
    fa_kernel<<<fg, 128>>>(qu, kk, M, vv, ctx);

    // output projection (fp32 out)
    ProjArgs po;
    po.s[0] = {ctx, Wo, bo, nullptr, nullptr, out, nullptr, 0};
    po.s[1] = po.s[0]; po.s[2] = po.s[0]; po.s[3] = po.s[0];
    dim3 pg1(DD / 128, MTOT / 128, 1);     // (4, 64, 1)
    proj_kernel<<<pg1, 256>>>(po);
}